// round 10
// baseline (speedup 1.0000x reference)
#include <cuda_runtime.h>
#include <cuda_bf16.h>
#include <cfloat>
#include <math.h>
#include <stdint.h>

// ---------------------------------------------------------------------------
// Problem constants
// ---------------------------------------------------------------------------
#define T_LEN   65536
#define DIM_S   64
#define DIM_A   8
#define DIM_C   16
#define HDIM    256
#define NTRANS  (T_LEN - 1)          // 65535 transitions
#define CHUNK   256                  // transitions per scan chunk
#define G_CHUNKS 256                 // ceil(65535 / 256)
#define NGROUP  16                   // chunks per super-group
#define NSUPER  16                   // number of super-groups

// Output layout (floats), concatenated in reference return order:
// log_alpha [T,16], log_beta [T,16], log_trs [T-1,16,16], log_pis [T,16], entropy [T-1,16]
static const size_t OFF_ALPHA = 0;
static const size_t OFF_BETA  = (size_t)T_LEN * DIM_C;
static const size_t OFF_TRS   = 2ull * T_LEN * DIM_C;
static const size_t OFF_PIS   = OFF_TRS + (size_t)NTRANS * DIM_C * DIM_C;
static const size_t OFF_ENT   = OFF_PIS + (size_t)T_LEN * DIM_C;

// ---------------------------------------------------------------------------
// Device scratch (static __device__ arrays; no allocation APIs)
// ---------------------------------------------------------------------------
__device__ float g_h1p[(size_t)T_LEN * HDIM];
__device__ float g_h1o[(size_t)T_LEN * HDIM];
__device__ float g_h2p[(size_t)T_LEN * HDIM];
__device__ float g_h2o[(size_t)T_LEN * HDIM];
__device__ float g_mean[(size_t)T_LEN * (DIM_C * DIM_A)];
__device__ float g_logits[(size_t)T_LEN * ((DIM_C + 1) * DIM_C)];
__device__ float g_Cmat[G_CHUNKS * 256];
__device__ float g_P  [NSUPER * NGROUP * 256];
__device__ float g_Suf[NSUPER * NGROUP * 256];
__device__ float g_Vs[(NSUPER + 1) * 16];
__device__ float g_Wsv[(NSUPER + 1) * 16];
__device__ float g_tr0[16];

// ---------------------------------------------------------------------------
// Split-bf16 helpers
// ---------------------------------------------------------------------------
__device__ __forceinline__ uint32_t pack2(__nv_bfloat16 a, __nv_bfloat16 b) {
    return (uint32_t)__bfloat16_as_ushort(a) |
           ((uint32_t)__bfloat16_as_ushort(b) << 16);
}
// Split (x, y) into hi/lo bf16 pairs packed as (low-half = first element).
__device__ __forceinline__ void split_pair(float x, float y,
                                           uint32_t& hi, uint32_t& lo) {
    __nv_bfloat16 xh = __float2bfloat16(x);
    __nv_bfloat16 yh = __float2bfloat16(y);
    float xr = x - __bfloat162float(xh);
    float yr = y - __bfloat162float(yh);
    hi = pack2(xh, yh);
    lo = pack2(__float2bfloat16(xr), __float2bfloat16(yr));
}

__device__ __forceinline__ void mma16816(float c[4], const uint32_t a[4],
                                         const uint32_t b[2]) {
    asm volatile(
        "mma.sync.aligned.m16n8k16.row.col.f32.bf16.bf16.f32 "
        "{%0,%1,%2,%3}, {%4,%5,%6,%7}, {%8,%9}, {%0,%1,%2,%3};\n"
        : "+f"(c[0]), "+f"(c[1]), "+f"(c[2]), "+f"(c[3])
        : "r"(a[0]), "r"(a[1]), "r"(a[2]), "r"(a[3]), "r"(b[0]), "r"(b[1]));
}

// ---------------------------------------------------------------------------
// Tensor-core GEMM: C[M x N] = act(A[M x K] @ W[K x N] + b), fp32 in/out,
// split-bf16 x3 mma (hi*hi + hi*lo + lo*hi), fp32 accumulate.
// 128x128x16 CTA tile, 8 warps (2x4), 64x32 warp tile, double-buffered smem.
// blockIdx.z selects between two independent problem instances.
// ---------------------------------------------------------------------------
#define BKW 9   // 32-bit words per smem row (8 data + 1 pad)

template <int K, int N, bool RELU>
__global__ __launch_bounds__(256, 2) void gemm_tc(
    const float* __restrict__ A0, const float* __restrict__ W0,
    const float* __restrict__ b0, float* __restrict__ C0,
    const float* __restrict__ A1, const float* __restrict__ W1,
    const float* __restrict__ b1, float* __restrict__ C1)
{
    constexpr int BM = 128, BN = 128, BK = 16;
    constexpr int NSLAB = K / BK;
    constexpr bool NG = (N % BN) != 0;   // N = 272 tail guards

    const float* __restrict__ A    = blockIdx.z ? A1 : A0;
    const float* __restrict__ W    = blockIdx.z ? W1 : W0;
    const float* __restrict__ bias = blockIdx.z ? b1 : b0;
    float*       __restrict__ C    = blockIdx.z ? C1 : C0;

    // smem planes per stage: [A_hi | A_lo | W_hi | W_lo], each BM*BKW words.
    constexpr int PL = BM * BKW;        // 1152 words
    __shared__ uint32_t sm[2][4 * PL];  // 36864 bytes total

    const int tid   = threadIdx.x;
    const int lane  = tid & 31;
    const int warp  = tid >> 5;
    const int warpM = (warp & 1) * 64;  // 2 warp rows
    const int warpN = (warp >> 1) * 32; // 4 warp cols
    const int g = lane >> 2;            // 0..7
    const int c = lane & 3;             // 0..3

    const int row0 = blockIdx.x * BM;
    const int col0 = blockIdx.y * BN;

    // Staging assignments
    const int am = tid >> 1;            // 0..127  (A row within tile)
    const int ak = (tid & 1) * 8;       // k offset 0 or 8
    const int wn = tid & 127;           // 0..127  (W col within tile)
    const int wk = (tid >> 7) * 8;      // k offset 0 or 8
    const int gcol = col0 + wn;
    const bool wvalid = (!NG) || (gcol < N);

    const float* Aptr = A + (size_t)(row0 + am) * K + ak;
    const float* Wptr = W + gcol;

    float acc[4][4][4];
#pragma unroll
    for (int mt = 0; mt < 4; mt++)
#pragma unroll
        for (int nt = 0; nt < 4; nt++)
#pragma unroll
            for (int q = 0; q < 4; q++) acc[mt][nt][q] = 0.f;

    float4 va0, va1;
    float  wv[8];

    auto prefetch = [&](int k0) {
        va0 = *reinterpret_cast<const float4*>(Aptr + k0);
        va1 = *reinterpret_cast<const float4*>(Aptr + k0 + 4);
#pragma unroll
        for (int i = 0; i < 8; i++)
            wv[i] = wvalid ? Wptr[(size_t)(k0 + wk + i) * N] : 0.f;
    };

    auto stage = [&](int st) {
        uint32_t* AH = &sm[st][0];
        uint32_t* AL = &sm[st][PL];
        uint32_t* WH = &sm[st][2 * PL];
        uint32_t* WL = &sm[st][3 * PL];
        uint32_t hi, lo;
        const int abase = am * BKW + (ak >> 1);
        split_pair(va0.x, va0.y, hi, lo); AH[abase + 0] = hi; AL[abase + 0] = lo;
        split_pair(va0.z, va0.w, hi, lo); AH[abase + 1] = hi; AL[abase + 1] = lo;
        split_pair(va1.x, va1.y, hi, lo); AH[abase + 2] = hi; AL[abase + 2] = lo;
        split_pair(va1.z, va1.w, hi, lo); AH[abase + 3] = hi; AL[abase + 3] = lo;
        const int wbase = wn * BKW + (wk >> 1);
#pragma unroll
        for (int j = 0; j < 4; j++) {
            split_pair(wv[2 * j], wv[2 * j + 1], hi, lo);
            WH[wbase + j] = hi; WL[wbase + j] = lo;
        }
    };

    auto compute = [&](int st) {
        const uint32_t* AH = &sm[st][0];
        const uint32_t* AL = &sm[st][PL];
        const uint32_t* WH = &sm[st][2 * PL];
        const uint32_t* WL = &sm[st][3 * PL];

        uint32_t bh[4][2], bl[4][2];
#pragma unroll
        for (int nt = 0; nt < 4; nt++) {
            const int nb = (warpN + nt * 8 + g) * BKW + c;
            bh[nt][0] = WH[nb];     bh[nt][1] = WH[nb + 4];
            bl[nt][0] = WL[nb];     bl[nt][1] = WL[nb + 4];
        }
#pragma unroll
        for (int mt = 0; mt < 4; mt++) {
            const int r0 = (warpM + mt * 16 + g) * BKW + c;
            const int r1 = r0 + 8 * BKW;
            uint32_t ah[4], al[4];
            ah[0] = AH[r0];     ah[1] = AH[r1];
            ah[2] = AH[r0 + 4]; ah[3] = AH[r1 + 4];
            al[0] = AL[r0];     al[1] = AL[r1];
            al[2] = AL[r0 + 4]; al[3] = AL[r1 + 4];
#pragma unroll
            for (int nt = 0; nt < 4; nt++) {
                mma16816(acc[mt][nt], ah, bh[nt]);
                mma16816(acc[mt][nt], ah, bl[nt]);
                mma16816(acc[mt][nt], al, bh[nt]);
            }
        }
    };

    // Pipeline
    prefetch(0);
    stage(0);
    __syncthreads();
    int st = 0;
#pragma unroll 1
    for (int s = 1; s < NSLAB; s++) {
        prefetch(s * BK);
        compute(st);
        stage(st ^ 1);
        __syncthreads();
        st ^= 1;
    }
    compute(st);

    // Epilogue
#pragma unroll
    for (int mt = 0; mt < 4; mt++) {
#pragma unroll
        for (int nt = 0; nt < 4; nt++) {
            const int col = col0 + warpN + nt * 8 + c * 2;
            if (NG && col >= N) continue;
            const float bx = bias[col];
            const float by = bias[col + 1];
            const int rowA = row0 + warpM + mt * 16 + g;
            float v0 = acc[mt][nt][0] + bx;
            float v1 = acc[mt][nt][1] + by;
            float v2 = acc[mt][nt][2] + bx;
            float v3 = acc[mt][nt][3] + by;
            if (RELU) {
                v0 = fmaxf(v0, 0.f); v1 = fmaxf(v1, 0.f);
                v2 = fmaxf(v2, 0.f); v3 = fmaxf(v3, 0.f);
            }
            *reinterpret_cast<float2*>(&C[(size_t)rowA * N + col]) =
                make_float2(v0, v1);
            *reinterpret_cast<float2*>(&C[(size_t)(rowA + 8) * N + col]) =
                make_float2(v2, v3);
        }
    }
}

// ---------------------------------------------------------------------------
// log_pis[t][c] = sum_a -0.5*((a - clip(mean))/std)^2 - logstd_a - 0.5*log(2pi)
// ---------------------------------------------------------------------------
__global__ void logpis_kernel(const float* __restrict__ mean,
                              const float* __restrict__ a_arr,
                              const float* __restrict__ a_log_std,
                              float* __restrict__ out_pis)
{
    __shared__ float s_inv_std[8];
    __shared__ float s_ls[8];
    if (threadIdx.x < 8) {
        float ls = tanhf(a_log_std[threadIdx.x]);
        ls = -5.0f + 3.5f * (ls + 1.0f);
        s_ls[threadIdx.x] = ls;
        s_inv_std[threadIdx.x] = expf(-ls);
    }
    __syncthreads();

    int idx = blockIdx.x * blockDim.x + threadIdx.x;
    if (idx >= T_LEN * DIM_C) return;

    float lsum = 0.f;
#pragma unroll
    for (int a = 0; a < 8; a++) lsum += s_ls[a];
    const float cst = -lsum - 4.0f * 1.8378770664093453f;

    const int t = idx >> 4;
    const int c = idx & 15;
    const float* m  = mean + (size_t)t * 128 + c * 8;
    const float* av = a_arr + (size_t)t * 8;
    float s = 0.f;
#pragma unroll
    for (int a = 0; a < 8; a++) {
        float mm = fminf(fmaxf(m[a], -10.f), 10.f);
        float z = (av[a] - mm) * s_inv_std[a];
        s = fmaf(z, z, s);
    }
    out_pis[idx] = -0.5f * s + cst;
}

// ---------------------------------------------------------------------------
// log_softmax over groups of 16, plus entropy, plus log_tr0 extraction
// ---------------------------------------------------------------------------
__global__ void softmax_kernel(const float* __restrict__ logits,
                               float* __restrict__ out_trs,
                               float* __restrict__ out_ent,
                               float* __restrict__ tr0)
{
    int idx = blockIdx.x * blockDim.x + threadIdx.x;
    if (idx >= T_LEN * 17) return;
    const int t = idx / 17;
    const int g = idx - t * 17;
    const bool is0 = (t == 0 && g == 16);
    const bool isn = (t >= 1 && g < 16);
    if (!is0 && !isn) return;

    const float* row = logits + (size_t)t * 272 + g * 16;
    float v[16];
#pragma unroll
    for (int q = 0; q < 4; q++)
        *reinterpret_cast<float4*>(&v[q * 4]) =
            *reinterpret_cast<const float4*>(&row[q * 4]);

    float mx = v[0];
#pragma unroll
    for (int j = 1; j < 16; j++) mx = fmaxf(mx, v[j]);
    float s = 0.f, ws = 0.f;
#pragma unroll
    for (int j = 0; j < 16; j++) {
        float d = v[j] - mx;
        float e = __expf(d);
        s += e;
        ws = fmaf(d, e, ws);
    }
    const float ls  = __logf(s);
    const float lse = mx + ls;

    if (is0) {
#pragma unroll
        for (int j = 0; j < 16; j++) tr0[j] = v[j] - lse;
    } else {
        float* o = out_trs + (size_t)(t - 1) * 256 + g * 16;
#pragma unroll
        for (int j = 0; j < 16; j++) o[j] = v[j] - lse;
        out_ent[(size_t)(t - 1) * 16 + g] = ls - ws / s;
    }
}

// ---------------------------------------------------------------------------
// Scan pass 1: per-chunk log-semiring transfer matrix
// ---------------------------------------------------------------------------
__global__ __launch_bounds__(256) void pass1_kernel(
    const float* __restrict__ trs, const float* __restrict__ pis,
    float* __restrict__ Cmat)
{
    const int g   = blockIdx.x;
    const int tid = threadIdx.x;
    const int i   = tid >> 4;
    const int j   = tid & 15;
    const int t0  = g * CHUNK;
    const int t1  = min(t0 + CHUNK, NTRANS);

    __shared__ float Cs[2][256];
    __shared__ float Ms[256];

    Cs[0][tid] = trs[(size_t)t0 * 256 + tid] + pis[(size_t)(t0 + 1) * 16 + j];
    int cb = 0;

    for (int t = t0 + 1; t < t1; t++) {
        float mv = trs[(size_t)t * 256 + tid] + pis[(size_t)(t + 1) * 16 + j];
        __syncthreads();
        Ms[tid] = mv;
        __syncthreads();

        float tmp[16];
        float mx = -FLT_MAX;
#pragma unroll
        for (int k = 0; k < 16; k++) {
            tmp[k] = Cs[cb][i * 16 + k] + Ms[k * 16 + j];
            mx = fmaxf(mx, tmp[k]);
        }
        float s = 0.f;
#pragma unroll
        for (int k = 0; k < 16; k++) s += __expf(tmp[k] - mx);
        Cs[cb ^ 1][tid] = mx + __logf(s);
        cb ^= 1;
    }
    __syncthreads();
    Cmat[g * 256 + tid] = Cs[cb][tid];
}

// ---------------------------------------------------------------------------
// Group prefix/suffix products over 16-chunk super-groups.
// ---------------------------------------------------------------------------
__global__ __launch_bounds__(256) void superprod_kernel(
    const float* __restrict__ Cmat, float* __restrict__ P, float* __restrict__ Suf)
{
    const int s   = blockIdx.x & 15;
    const int dir = blockIdx.x >> 4;
    const int tid = threadIdx.x;
    const int i   = tid >> 4;
    const int j   = tid & 15;

    __shared__ float Cs[2][256];
    __shared__ float Ms[256];
    int cb = 0;

    if (dir == 0) {
        Cs[0][tid] = Cmat[(s * 16) * 256 + tid];
        P[(s * 16) * 256 + tid] = Cs[0][tid];
        for (int r = 1; r < 16; r++) {
            float mv = Cmat[(s * 16 + r) * 256 + tid];
            __syncthreads();
            Ms[tid] = mv;
            __syncthreads();
            float tmp[16];
            float mx = -FLT_MAX;
#pragma unroll
            for (int k = 0; k < 16; k++) {
                tmp[k] = Cs[cb][i * 16 + k] + Ms[k * 16 + j];
                mx = fmaxf(mx, tmp[k]);
            }
            float ssum = 0.f;
#pragma unroll
            for (int k = 0; k < 16; k++) ssum += __expf(tmp[k] - mx);
            float res = mx + __logf(ssum);
            Cs[cb ^ 1][tid] = res;
            P[(s * 16 + r) * 256 + tid] = res;
            cb ^= 1;
        }
    } else {
        Cs[0][tid] = Cmat[(s * 16 + 15) * 256 + tid];
        Suf[(s * 16 + 15) * 256 + tid] = Cs[0][tid];
        for (int r = 14; r >= 0; r--) {
            float mv = Cmat[(s * 16 + r) * 256 + tid];
            __syncthreads();
            Ms[tid] = mv;
            __syncthreads();
            float tmp[16];
            float mx = -FLT_MAX;
#pragma unroll
            for (int k = 0; k < 16; k++) {
                tmp[k] = Ms[i * 16 + k] + Cs[cb][k * 16 + j];
                mx = fmaxf(mx, tmp[k]);
            }
            float ssum = 0.f;
#pragma unroll
            for (int k = 0; k < 16; k++) ssum += __expf(tmp[k] - mx);
            float res = mx + __logf(ssum);
            Cs[cb ^ 1][tid] = res;
            Suf[(s * 16 + r) * 256 + tid] = res;
            cb ^= 1;
        }
    }
}

// ---------------------------------------------------------------------------
// Serial combine over SUPER-group boundaries (16 steps each direction).
// ---------------------------------------------------------------------------
__global__ void combine2_kernel(const float* __restrict__ P,
                                const float* __restrict__ tr0,
                                const float* __restrict__ pis,
                                float* __restrict__ Vs, float* __restrict__ Wsv,
                                float* __restrict__ out_beta)
{
    const int lane = threadIdx.x;
    if (lane >= 16) return;
    const unsigned mask = 0xFFFFu;

    if (blockIdx.x == 0) {
        float v = tr0[lane] + pis[lane];   // a0
        Vs[lane] = v;
        for (int s = 0; s < NSUPER; s++) {
            const float* S = P + (s * 16 + 15) * 256;
            float tmp[16];
#pragma unroll
            for (int i = 0; i < 16; i++)
                tmp[i] = __shfl_sync(mask, v, i) + S[i * 16 + lane];
            float mx = tmp[0];
#pragma unroll
            for (int i = 1; i < 16; i++) mx = fmaxf(mx, tmp[i]);
            float ssum = 0.f;
#pragma unroll
            for (int i = 0; i < 16; i++) ssum += __expf(tmp[i] - mx);
            v = mx + __logf(ssum);
            Vs[(s + 1) * 16 + lane] = v;
        }
    } else {
        float w = 0.f;
        Wsv[NSUPER * 16 + lane] = 0.f;
        out_beta[(size_t)(T_LEN - 1) * 16 + lane] = 0.f;
        for (int s = NSUPER - 1; s >= 0; s--) {
            const float* S = P + (s * 16 + 15) * 256 + lane * 16;
            float tmp[16];
#pragma unroll
            for (int j = 0; j < 16; j++)
                tmp[j] = __shfl_sync(mask, w, j) + S[j];
            float mx = tmp[0];
#pragma unroll
            for (int j = 1; j < 16; j++) mx = fmaxf(mx, tmp[j]);
            float ssum = 0.f;
#pragma unroll
            for (int j = 0; j < 16; j++) ssum += __expf(tmp[j] - mx);
            w = mx + __logf(ssum);
            Wsv[s * 16 + lane] = w;
        }
    }
}

// ---------------------------------------------------------------------------
// Scan pass 2: expand alpha/beta inside each chunk.
// ---------------------------------------------------------------------------
__global__ void pass2_kernel(const float* __restrict__ trs,
                             const float* __restrict__ pis,
                             const float* __restrict__ P,
                             const float* __restrict__ Suf,
                             const float* __restrict__ Vs,
                             const float* __restrict__ Wsv,
                             float* __restrict__ out_alpha,
                             float* __restrict__ out_beta)
{
    const int lane = threadIdx.x;
    if (lane >= 16) return;
    const unsigned mask = 0xFFFFu;
    const int b = blockIdx.x;

    if (b < G_CHUNKS) {   // forward
        const int g  = b;
        const int s  = g >> 4;
        const int r  = g & 15;
        const int t0 = g * CHUNK;
        const int t1 = min(t0 + CHUNK, NTRANS);

        float v;
        {
            float vs = Vs[s * 16 + lane];
            if (r == 0) {
                v = vs;
            } else {
                const float* Pm = P + (s * 16 + (r - 1)) * 256;
                float tmp[16];
#pragma unroll
                for (int i = 0; i < 16; i++)
                    tmp[i] = __shfl_sync(mask, vs, i) + Pm[i * 16 + lane];
                float mx = tmp[0];
#pragma unroll
                for (int i = 1; i < 16; i++) mx = fmaxf(mx, tmp[i]);
                float ssum = 0.f;
#pragma unroll
                for (int i = 0; i < 16; i++) ssum += __expf(tmp[i] - mx);
                v = mx + __logf(ssum);
            }
        }
        if (g == 0) out_alpha[lane] = v;

        for (int t = t0; t < t1; t++) {
            const float* M = trs + (size_t)t * 256;
            float tmp[16];
#pragma unroll
            for (int i = 0; i < 16; i++)
                tmp[i] = __shfl_sync(mask, v, i) + M[i * 16 + lane];
            float mx = tmp[0];
#pragma unroll
            for (int i = 1; i < 16; i++) mx = fmaxf(mx, tmp[i]);
            float ssum = 0.f;
#pragma unroll
            for (int i = 0; i < 16; i++) ssum += __expf(tmp[i] - mx);
            v = mx + __logf(ssum) + pis[(size_t)(t + 1) * 16 + lane];
            out_alpha[(size_t)(t + 1) * 16 + lane] = v;
        }
    } else {              // backward
        const int g  = b - G_CHUNKS;
        const int s  = g >> 4;
        const int r  = g & 15;
        const int t0 = g * CHUNK;
        const int t1 = min(t0 + CHUNK, NTRANS);

        float w;
        {
            float wsv = Wsv[(s + 1) * 16 + lane];
            if (r == 15) {
                w = wsv;
            } else {
                const float* Sf = Suf + (s * 16 + (r + 1)) * 256 + lane * 16;
                float tmp[16];
#pragma unroll
                for (int j = 0; j < 16; j++)
                    tmp[j] = Sf[j] + __shfl_sync(mask, wsv, j);
                float mx = tmp[0];
#pragma unroll
                for (int j = 1; j < 16; j++) mx = fmaxf(mx, tmp[j]);
                float ssum = 0.f;
#pragma unroll
                for (int j = 0; j < 16; j++) ssum += __expf(tmp[j] - mx);
                w = mx + __logf(ssum);
            }
        }

        for (int t = t1 - 1; t >= t0; t--) {
            const float* M = trs + (size_t)t * 256 + lane * 16;
            float u = w + pis[(size_t)(t + 1) * 16 + lane];
            float tmp[16];
#pragma unroll
            for (int j = 0; j < 16; j++)
                tmp[j] = __shfl_sync(mask, u, j) + M[j];
            float mx = tmp[0];
#pragma unroll
            for (int j = 1; j < 16; j++) mx = fmaxf(mx, tmp[j]);
            float ssum = 0.f;
#pragma unroll
            for (int j = 0; j < 16; j++) ssum += __expf(tmp[j] - mx);
            w = mx + __logf(ssum);
            out_beta[(size_t)t * 16 + lane] = w;
        }
    }
}

// ---------------------------------------------------------------------------
// Host launcher
// ---------------------------------------------------------------------------
extern "C" void kernel_launch(void* const* d_in, const int* in_sizes, int n_in,
                              void* d_out, int out_size)
{
    const float* s_arr = (const float*)d_in[0];
    const float* a_arr = (const float*)d_in[1];
    const float* pW1 = (const float*)d_in[2];  const float* pb1 = (const float*)d_in[3];
    const float* pW2 = (const float*)d_in[4];  const float* pb2 = (const float*)d_in[5];
    const float* pW3 = (const float*)d_in[6];  const float* pb3 = (const float*)d_in[7];
    const float* oW1 = (const float*)d_in[8];  const float* ob1 = (const float*)d_in[9];
    const float* oW2 = (const float*)d_in[10]; const float* ob2 = (const float*)d_in[11];
    const float* oW3 = (const float*)d_in[12]; const float* ob3 = (const float*)d_in[13];
    const float* als = (const float*)d_in[14];

    float* out = (float*)d_out;
    float* out_alpha = out + OFF_ALPHA;
    float* out_beta  = out + OFF_BETA;
    float* out_trs   = out + OFF_TRS;
    float* out_pis   = out + OFF_PIS;
    float* out_ent   = out + OFF_ENT;

    float *h1p, *h1o, *h2p, *h2o, *meanb, *logitsb, *Cmat, *Pm, *Sf, *Vs, *Wsv, *tr0;
    cudaGetSymbolAddress((void**)&h1p,    g_h1p);
    cudaGetSymbolAddress((void**)&h1o,    g_h1o);
    cudaGetSymbolAddress((void**)&h2p,    g_h2p);
    cudaGetSymbolAddress((void**)&h2o,    g_h2o);
    cudaGetSymbolAddress((void**)&meanb,  g_mean);
    cudaGetSymbolAddress((void**)&logitsb,g_logits);
    cudaGetSymbolAddress((void**)&Cmat,   g_Cmat);
    cudaGetSymbolAddress((void**)&Pm,     g_P);
    cudaGetSymbolAddress((void**)&Sf,     g_Suf);
    cudaGetSymbolAddress((void**)&Vs,     g_Vs);
    cudaGetSymbolAddress((void**)&Wsv,    g_Wsv);
    cudaGetSymbolAddress((void**)&tr0,    g_tr0);

    const int MB = T_LEN / 128;   // 512 row tiles

    // Layer 1 (both MLPs fused via blockIdx.z)
    gemm_tc<64, 256, true ><<<dim3(MB, 2, 2), 256>>>(
        s_arr, pW1, pb1, h1p,  s_arr, oW1, ob1, h1o);
    // Layer 2 (both MLPs fused)
    gemm_tc<256, 256, true ><<<dim3(MB, 2, 2), 256>>>(
        h1p, pW2, pb2, h2p,  h1o, oW2, ob2, h2o);
    // Layer 3 (different N -> separate launches)
    gemm_tc<256, 128, false><<<dim3(MB, 1, 1), 256>>>(
        h2p, pW3, pb3, meanb,  h2p, pW3, pb3, meanb);
    gemm_tc<256, 272, false><<<dim3(MB, 3, 1), 256>>>(
        h2o, oW3, ob3, logitsb,  h2o, oW3, ob3, logitsb);

    // Post-processing
    logpis_kernel<<<(T_LEN * DIM_C + 255) / 256, 256>>>(meanb, a_arr, als, out_pis);
    softmax_kernel<<<(T_LEN * 17 + 255) / 256, 256>>>(logitsb, out_trs, out_ent, tr0);

    // Parallel log-semiring scans
    pass1_kernel<<<G_CHUNKS, 256>>>(out_trs, out_pis, Cmat);
    superprod_kernel<<<2 * NSUPER, 256>>>(Cmat, Pm, Sf);
    combine2_kernel<<<2, 32>>>(Pm, tr0, out_pis, Vs, Wsv, out_beta);
    pass2_kernel<<<2 * G_CHUNKS, 32>>>(out_trs, out_pis, Pm, Sf, Vs, Wsv,
                                       out_alpha, out_beta);
}

// round 13
// speedup vs baseline: 1.1033x; 1.1033x over previous
#include <cuda_runtime.h>
#include <cuda_bf16.h>
#include <cfloat>
#include <math.h>
#include <stdint.h>

#define T_LEN   65536
#define DIM_A   8
#define DIM_C   16
#define NTRANS  (T_LEN - 1)
#define CHUNK   256
#define G_CHUNKS 256
#define NSUPER  16

static const size_t OFF_ALPHA = 0;
static const size_t OFF_BETA  = (size_t)T_LEN * DIM_C;
static const size_t OFF_TRS   = 2ull * T_LEN * DIM_C;
static const size_t OFF_PIS   = OFF_TRS + (size_t)NTRANS * DIM_C * DIM_C;
static const size_t OFF_ENT   = OFF_PIS + (size_t)T_LEN * DIM_C;

// ---------------- device scratch ----------------
__device__ __nv_bfloat16 g_sH [(size_t)T_LEN * 64];
__device__ __nv_bfloat16 g_sL [(size_t)T_LEN * 64];
__device__ __nv_bfloat16 g_h1pH[(size_t)T_LEN * 256];
__device__ __nv_bfloat16 g_h1pL[(size_t)T_LEN * 256];
__device__ __nv_bfloat16 g_h1oH[(size_t)T_LEN * 256];
__device__ __nv_bfloat16 g_h1oL[(size_t)T_LEN * 256];
__device__ __nv_bfloat16 g_h2pH[(size_t)T_LEN * 256];
__device__ __nv_bfloat16 g_h2pL[(size_t)T_LEN * 256];
__device__ __nv_bfloat16 g_h2oH[(size_t)T_LEN * 256];
__device__ __nv_bfloat16 g_h2oL[(size_t)T_LEN * 256];
__device__ float g_mean[(size_t)T_LEN * 128];
__device__ float g_logits[(size_t)T_LEN * 272];
__device__ float g_Cmat[G_CHUNKS * 256];
__device__ float g_P  [G_CHUNKS * 256];
__device__ float g_Suf[G_CHUNKS * 256];
__device__ float g_Vs[(NSUPER + 1) * 16];
__device__ float g_Wsv[(NSUPER + 1) * 16];
__device__ float g_tr0[16];

#define WT_NPAD 384
#define WT_KPAD 256
#define WT_SZ   (WT_NPAD * WT_KPAD)
__device__ __nv_bfloat16 g_wtH[6 * WT_SZ];
__device__ __nv_bfloat16 g_wtL[6 * WT_SZ];

// ---------------- helpers ----------------
__device__ __forceinline__ uint32_t s2u(const void* p) {
    uint32_t a;
    asm("{ .reg .u64 t; cvta.to.shared.u64 t, %1; cvt.u32.u64 %0, t; }" : "=r"(a) : "l"(p));
    return a;
}
__device__ __forceinline__ uint32_t pack2(__nv_bfloat16 a, __nv_bfloat16 b) {
    return (uint32_t)__bfloat16_as_ushort(a) | ((uint32_t)__bfloat16_as_ushort(b) << 16);
}
__device__ __forceinline__ void cpa16(uint32_t d, const void* s) {
    asm volatile("cp.async.cg.shared.global [%0], [%1], 16;" :: "r"(d), "l"(s) : "memory");
}
#define CP_COMMIT() asm volatile("cp.async.commit_group;" ::: "memory")
#define LDM4(r, a) \
    asm volatile("ldmatrix.sync.aligned.m8n8.x4.shared.b16 {%0,%1,%2,%3}, [%4];" \
        : "=r"((r)[0]), "=r"((r)[1]), "=r"((r)[2]), "=r"((r)[3]) : "r"(a))
__device__ __forceinline__ void mma16816(float c[4], const uint32_t a[4], const uint32_t b[2]) {
    asm volatile(
        "mma.sync.aligned.m16n8k16.row.col.f32.bf16.bf16.f32 "
        "{%0,%1,%2,%3}, {%4,%5,%6,%7}, {%8,%9}, {%0,%1,%2,%3};\n"
        : "+f"(c[0]), "+f"(c[1]), "+f"(c[2]), "+f"(c[3])
        : "r"(a[0]), "r"(a[1]), "r"(a[2]), "r"(a[3]), "r"(b[0]), "r"(b[1]));
}
#define SWZ64(o) ((o) ^ (((o) >> 3) & 0x30))

// ---------------- prep kernels ----------------
__global__ void prep_weights(const float* __restrict__ W0, const float* __restrict__ W1,
                             const float* __restrict__ W2, const float* __restrict__ W3,
                             const float* __restrict__ W4, const float* __restrict__ W5,
                             __nv_bfloat16* __restrict__ WH, __nv_bfloat16* __restrict__ WL)
{
    int idx = blockIdx.x * blockDim.x + threadIdx.x;
    if (idx >= 6 * WT_SZ) return;
    const int layer = idx / WT_SZ;
    const int rem = idx - layer * WT_SZ;
    const int n = rem >> 8, k = rem & 255;
    const int Ks[6] = {64, 64, 256, 256, 256, 256};
    const int Ns[6] = {256, 256, 256, 256, 128, 272};
    const float* Ws[6] = {W0, W1, W2, W3, W4, W5};
    float v = 0.f;
    if (n < Ns[layer] && k < Ks[layer]) v = Ws[layer][(size_t)k * Ns[layer] + n];
    __nv_bfloat16 h = __float2bfloat16(v);
    WH[idx] = h;
    WL[idx] = __float2bfloat16(v - __bfloat162float(h));
}

__global__ void prep_sact(const float* __restrict__ s,
                          __nv_bfloat16* __restrict__ H, __nv_bfloat16* __restrict__ L)
{
    int idx = blockIdx.x * blockDim.x + threadIdx.x;
    if (idx >= T_LEN * 64) return;
    float v = s[idx];
    __nv_bfloat16 h = __float2bfloat16(v);
    H[idx] = h;
    L[idx] = __float2bfloat16(v - __bfloat162float(h));
}

// ---------------- GEMM: ldmatrix + cp.async + split-bf16 x3 mma ----------------
// smem stage: [A_hi 8K | A_lo 8K | W_hi 8K | W_lo 8K]; rows = 64B (32 bf16), SW64.
#define STG 32768
#define SMEM_DYN (2 * STG + 1024)

template <int K, int N, bool RELU, bool NG, bool SPLIT>
__global__ __launch_bounds__(256, 2) void gemm6(
    const __nv_bfloat16* __restrict__ AH0, const __nv_bfloat16* __restrict__ AL0,
    const __nv_bfloat16* __restrict__ WH0, const __nv_bfloat16* __restrict__ WL0,
    const float* __restrict__ b0, float* __restrict__ Cf0,
    __nv_bfloat16* __restrict__ CH0, __nv_bfloat16* __restrict__ CL0,
    const __nv_bfloat16* __restrict__ AH1, const __nv_bfloat16* __restrict__ AL1,
    const __nv_bfloat16* __restrict__ WH1, const __nv_bfloat16* __restrict__ WL1,
    const float* __restrict__ b1, float* __restrict__ Cf1,
    __nv_bfloat16* __restrict__ CH1, __nv_bfloat16* __restrict__ CL1)
{
    constexpr int NSLAB = K / 32;
    const __nv_bfloat16* AH = blockIdx.z ? AH1 : AH0;
    const __nv_bfloat16* AL = blockIdx.z ? AL1 : AL0;
    const __nv_bfloat16* WH = blockIdx.z ? WH1 : WH0;
    const __nv_bfloat16* WL = blockIdx.z ? WL1 : WL0;
    const float* bias = blockIdx.z ? b1 : b0;
    float* Cf = blockIdx.z ? Cf1 : Cf0;
    __nv_bfloat16* CH = blockIdx.z ? CH1 : CH0;
    __nv_bfloat16* CL = blockIdx.z ? CL1 : CL0;

    extern __shared__ uint8_t dsm[];
    const uint32_t smb = (s2u(dsm) + 1023u) & ~1023u;

    const int tid = threadIdx.x, lane = tid & 31, wid = tid >> 5;
    const int warpM = (wid & 1) * 64, warpN = (wid >> 1) * 32;
    const int row0 = blockIdx.x * 128, col0 = blockIdx.y * 128;

    // staging: 2 threads per row, 2x16B chunks each, per plane
    const int m = tid >> 1, half = tid & 1;
    const __nv_bfloat16* pAH = AH + (size_t)(row0 + m) * K + half * 16;
    const __nv_bfloat16* pAL = AL + (size_t)(row0 + m) * K + half * 16;
    const __nv_bfloat16* pWH = WH + (size_t)(col0 + m) * WT_KPAD + half * 16;
    const __nv_bfloat16* pWL = WL + (size_t)(col0 + m) * WT_KPAD + half * 16;
    const uint32_t dsw0 = SWZ64((uint32_t)(m * 64 + half * 32));
    const uint32_t dsw1 = SWZ64((uint32_t)(m * 64 + half * 32 + 16));

    auto issue = [&](int s, int st) {
        const uint32_t SB = smb + st * STG;
        cpa16(SB + dsw0,         pAH + s * 32);
        cpa16(SB + dsw1,         pAH + s * 32 + 8);
        cpa16(SB + 8192  + dsw0, pAL + s * 32);
        cpa16(SB + 8192  + dsw1, pAL + s * 32 + 8);
        cpa16(SB + 16384 + dsw0, pWH + s * 32);
        cpa16(SB + 16384 + dsw1, pWH + s * 32 + 8);
        cpa16(SB + 24576 + dsw0, pWL + s * 32);
        cpa16(SB + 24576 + dsw1, pWL + s * 32 + 8);
        CP_COMMIT();
    };

    float acc[4][4][4];
#pragma unroll
    for (int mt = 0; mt < 4; mt++)
#pragma unroll
        for (int nt = 0; nt < 4; nt++)
#pragma unroll
            for (int q = 0; q < 4; q++) acc[mt][nt][q] = 0.f;

    // ldmatrix per-lane row mapping
    const int mat = lane >> 3, rin = lane & 7;
    const int a_row = warpM + ((mat & 1) << 3) + rin;   // A: mats 0/2 -> m+0, 1/3 -> m+8
    const int a_kb  = (mat >> 1) << 4;                  //    mats 0/1 -> k0-7, 2/3 -> k8-15
    const int b_row = warpN + ((mat >> 1) << 3) + rin;  // B: mats 0/1 -> n+0, 2/3 -> n+8
    const int b_kb  = (mat & 1) << 4;                   //    mats 0/2 -> k0-7, 1/3 -> k8-15

    auto compute = [&](int st) {
        const uint32_t SB = smb + st * STG;
#pragma unroll
        for (int ks = 0; ks < 2; ks++) {
            uint32_t bh[2][4], bl[2][4];
#pragma unroll
            for (int p = 0; p < 2; p++) {
                uint32_t off = (uint32_t)((b_row + p * 16) * 64 + ks * 32 + b_kb);
                uint32_t sw = SWZ64(off);
                LDM4(bh[p], SB + 16384 + sw);
                LDM4(bl[p], SB + 24576 + sw);
            }
#pragma unroll
            for (int mt = 0; mt < 4; mt++) {
                uint32_t off = (uint32_t)((a_row + mt * 16) * 64 + ks * 32 + a_kb);
                uint32_t sw = SWZ64(off);
                uint32_t ah[4], al[4];
                LDM4(ah, SB + sw);
                LDM4(al, SB + 8192 + sw);
#pragma unroll
                for (int nt = 0; nt < 4; nt++) {
                    const int p = nt >> 1, ix = (nt & 1) * 2;
                    uint32_t bbh[2] = {bh[p][ix], bh[p][ix + 1]};
                    uint32_t bbl[2] = {bl[p][ix], bl[p][ix + 1]};
                    mma16816(acc[mt][nt], ah, bbh);
                    mma16816(acc[mt][nt], ah, bbl);
                    mma16816(acc[mt][nt], al, bbh);
                }
            }
        }
    };

    issue(0, 0);
    if (NSLAB > 1) issue(1, 1);
#pragma unroll 1
    for (int s = 0; s < NSLAB; s++) {
        if (s < NSLAB - 1) asm volatile("cp.async.wait_group 1;" ::: "memory");
        else               asm volatile("cp.async.wait_group 0;" ::: "memory");
        __syncthreads();
        compute(s & 1);
        __syncthreads();
        if (s + 2 < NSLAB) issue(s + 2, s & 1);
    }

    // epilogue
    const int g = lane >> 2, c = lane & 3;
#pragma unroll
    for (int mt = 0; mt < 4; mt++) {
#pragma unroll
        for (int nt = 0; nt < 4; nt++) {
            const int col = col0 + warpN + nt * 8 + c * 2;
            if (NG && col >= N) continue;
            const float bx = bias[col], by = bias[col + 1];
            const int rw = row0 + warpM + mt * 16 + g;
            float v0 = acc[mt][nt][0] + bx, v1 = acc[mt][nt][1] + by;
            float v2 = acc[mt][nt][2] + bx, v3 = acc[mt][nt][3] + by;
            if (RELU) {
                v0 = fmaxf(v0, 0.f); v1 = fmaxf(v1, 0.f);
                v2 = fmaxf(v2, 0.f); v3 = fmaxf(v3, 0.f);
            }
            if constexpr (SPLIT) {
                __nv_bfloat16 h0 = __float2bfloat16(v0), h1 = __float2bfloat16(v1);
                __nv_bfloat16 h2 = __float2bfloat16(v2), h3 = __float2bfloat16(v3);
                *(uint32_t*)&CH[(size_t)rw * N + col] = pack2(h0, h1);
                *(uint32_t*)&CL[(size_t)rw * N + col] =
                    pack2(__float2bfloat16(v0 - __bfloat162float(h0)),
                          __float2bfloat16(v1 - __bfloat162float(h1)));
                *(uint32_t*)&CH[(size_t)(rw + 8) * N + col] = pack2(h2, h3);
                *(uint32_t*)&CL[(size_t)(rw + 8) * N + col] =
                    pack2(__float2bfloat16(v2 - __bfloat162float(h2)),
                          __float2bfloat16(v3 - __bfloat162float(h3)));
            } else {
                *(float2*)&Cf[(size_t)rw * N + col] = make_float2(v0, v1);
                *(float2*)&Cf[(size_t)(rw + 8) * N + col] = make_float2(v2, v3);
            }
        }
    }
}

// ---------------- log_pis ----------------
__global__ void logpis_kernel(const float* __restrict__ mean, const float* __restrict__ a_arr,
                              const float* __restrict__ a_log_std, float* __restrict__ out_pis)
{
    __shared__ float s_inv_std[8], s_ls[8];
    if (threadIdx.x < 8) {
        float ls = tanhf(a_log_std[threadIdx.x]);
        ls = -5.0f + 3.5f * (ls + 1.0f);
        s_ls[threadIdx.x] = ls;
        s_inv_std[threadIdx.x] = expf(-ls);
    }
    __syncthreads();
    int idx = blockIdx.x * blockDim.x + threadIdx.x;
    if (idx >= T_LEN * DIM_C) return;
    float lsum = 0.f;
#pragma unroll
    for (int a = 0; a < 8; a++) lsum += s_ls[a];
    const float cst = -lsum - 4.0f * 1.8378770664093453f;
    const int t = idx >> 4, c = idx & 15;
    const float* m = mean + (size_t)t * 128 + c * 8;
    const float* av = a_arr + (size_t)t * 8;
    float s = 0.f;
#pragma unroll
    for (int a = 0; a < 8; a++) {
        float mm = fminf(fmaxf(m[a], -10.f), 10.f);
        float z = (av[a] - mm) * s_inv_std[a];
        s = fmaf(z, z, s);
    }
    out_pis[idx] = -0.5f * s + cst;
}

// ---------------- log_softmax + entropy + tr0 ----------------
__global__ void softmax_kernel(const float* __restrict__ logits, float* __restrict__ out_trs,
                               float* __restrict__ out_ent, float* __restrict__ tr0)
{
    int idx = blockIdx.x * blockDim.x + threadIdx.x;
    if (idx >= T_LEN * 17) return;
    const int t = idx / 17, g = idx - t * 17;
    const bool is0 = (t == 0 && g == 16);
    const bool isn = (t >= 1 && g < 16);
    if (!is0 && !isn) return;
    const float* row = logits + (size_t)t * 272 + g * 16;
    float v[16];
#pragma unroll
    for (int q = 0; q < 4; q++)
        *reinterpret_cast<float4*>(&v[q*4]) = *reinterpret_cast<const float4*>(&row[q*4]);
    float mx = v[0];
#pragma unroll
    for (int j = 1; j < 16; j++) mx = fmaxf(mx, v[j]);
    float s = 0.f, ws = 0.f;
#pragma unroll
    for (int j = 0; j < 16; j++) { float d = v[j]-mx; float e = __expf(d); s += e; ws = fmaf(d, e, ws); }
    const float ls = __logf(s), lse = mx + ls;
    if (is0) {
#pragma unroll
        for (int j = 0; j < 16; j++) tr0[j] = v[j] - lse;
    } else {
        float* o = out_trs + (size_t)(t-1) * 256 + g * 16;
#pragma unroll
        for (int j = 0; j < 16; j++) o[j] = v[j] - lse;
        out_ent[(size_t)(t-1) * 16 + g] = ls - ws / s;
    }
}

// ---------------- scan pass 1 ----------------
__global__ __launch_bounds__(256) void pass1_kernel(
    const float* __restrict__ trs, const float* __restrict__ pis, float* __restrict__ Cmat)
{
    const int g = blockIdx.x, tid = threadIdx.x;
    const int i = tid >> 4, j = tid & 15;
    const int t0 = g * CHUNK, t1 = min(t0 + CHUNK, NTRANS);
    __shared__ float Cs[2][256], Ms[256];
    Cs[0][tid] = trs[(size_t)t0 * 256 + tid] + pis[(size_t)(t0+1) * 16 + j];
    int cb = 0;
    for (int t = t0 + 1; t < t1; t++) {
        float mv = trs[(size_t)t * 256 + tid] + pis[(size_t)(t+1) * 16 + j];
        __syncthreads();
        Ms[tid] = mv;
        __syncthreads();
        float tmp[16], mx = -FLT_MAX;
#pragma unroll
        for (int k = 0; k < 16; k++) { tmp[k] = Cs[cb][i*16+k] + Ms[k*16+j]; mx = fmaxf(mx, tmp[k]); }
        float s = 0.f;
#pragma unroll
        for (int k = 0; k < 16; k++) s += __expf(tmp[k] - mx);
        Cs[cb^1][tid] = mx + __logf(s);
        cb ^= 1;
    }
    __syncthreads();
    Cmat[g * 256 + tid] = Cs[cb][tid];
}

// ---------------- group prefix/suffix products ----------------
__global__ __launch_bounds__(256) void superprod_kernel(
    const float* __restrict__ Cmat, float* __restrict__ P, float* __restrict__ Suf)
{
    const int s = blockIdx.x & 15, dir = blockIdx.x >> 4, tid = threadIdx.x;
    const int i = tid >> 4, j = tid & 15;
    __shared__ float Cs[2][256], Ms[256];
    int cb = 0;
    if (dir == 0) {
        Cs[0][tid] = Cmat[(s*16) * 256 + tid];
        P[(s*16) * 256 + tid] = Cs[0][tid];
        for (int r = 1; r < 16; r++) {
            float mv = Cmat[(s*16+r) * 256 + tid];
            __syncthreads(); Ms[tid] = mv; __syncthreads();
            float tmp[16], mx = -FLT_MAX;
#pragma unroll
            for (int k = 0; k < 16; k++) { tmp[k] = Cs[cb][i*16+k] + Ms[k*16+j]; mx = fmaxf(mx, tmp[k]); }
            float ss = 0.f;
#pragma unroll
            for (int k = 0; k < 16; k++) ss += __expf(tmp[k] - mx);
            float res = mx + __logf(ss);
            Cs[cb^1][tid] = res;
            P[(s*16+r) * 256 + tid] = res;
            cb ^= 1;
        }
    } else {
        Cs[0][tid] = Cmat[(s*16+15) * 256 + tid];
        Suf[(s*16+15) * 256 + tid] = Cs[0][tid];
        for (int r = 14; r >= 0; r--) {
            float mv = Cmat[(s*16+r) * 256 + tid];
            __syncthreads(); Ms[tid] = mv; __syncthreads();
            float tmp[16], mx = -FLT_MAX;
#pragma unroll
            for (int k = 0; k < 16; k++) { tmp[k] = Ms[i*16+k] + Cs[cb][k*16+j]; mx = fmaxf(mx, tmp[k]); }
            float ss = 0.f;
#pragma unroll
            for (int k = 0; k < 16; k++) ss += __expf(tmp[k] - mx);
            float res = mx + __logf(ss);
            Cs[cb^1][tid] = res;
            Suf[(s*16+r) * 256 + tid] = res;
            cb ^= 1;
        }
    }
}

// ---------------- serial combine ----------------
__global__ void combine2_kernel(const float* __restrict__ P, const float* __restrict__ tr0,
                                const float* __restrict__ pis, float* __restrict__ Vs,
                                float* __restrict__ Wsv, float* __restrict__ out_beta)
{
    const int lane = threadIdx.x;
    if (lane >= 16) return;
    const unsigned mask = 0xFFFFu;
    if (blockIdx.x == 0) {
        float v = tr0[lane] + pis[lane];
        Vs[lane] = v;
        for (int s = 0; s < NSUPER; s++) {
            const float* S = P + (s*16+15) * 256;
            float tmp[16];
#pragma unroll
            for (int i = 0; i < 16; i++) tmp[i] = __shfl_sync(mask, v, i) + S[i*16+lane];
            float mx = tmp[0];
#pragma unroll
            for (int i = 1; i < 16; i++) mx = fmaxf(mx, tmp[i]);
            float ss = 0.f;
#pragma unroll
            for (int i = 0; i < 16; i++) ss += __expf(tmp[i] - mx);
            v = mx + __logf(ss);
            Vs[(s+1)*16 + lane] = v;
        }
    } else {
        float w = 0.f;
        Wsv[NSUPER*16 + lane] = 0.f;
        out_beta[(size_t)(T_LEN-1) * 16 + lane] = 0.f;
        for (int s = NSUPER - 1; s >= 0; s--) {
            const float* S = P + (s*16+15) * 256 + lane * 16;
            float tmp[16];
#pragma unroll
            for (int j = 0; j < 16; j++) tmp[j] = __shfl_sync(mask, w, j) + S[j];
            float mx = tmp[0];
#pragma unroll
            for (int j = 1; j < 16; j++) mx = fmaxf(mx, tmp[j]);
            float ss = 0.f;
#pragma unroll
            for (int j = 0; j < 16; j++) ss += __expf(tmp[j] - mx);
            w = mx + __logf(ss);
            Wsv[s*16 + lane] = w;
        }
    }
}

// ---------------- scan pass 2 ----------------
__global__ void pass2_kernel(const float* __restrict__ trs, const float* __restrict__ pis,
                             const float* __restrict__ P, const float* __restrict__ Suf,
                             const float* __restrict__ Vs, const float* __restrict__ Wsv,
                             float* __restrict__ out_alpha, float* __restrict__ out_beta)
{
    const int lane = threadIdx.x;
    if (lane >= 16) return;
    const unsigned mask = 0xFFFFu;
    const int b = blockIdx.x;
    if (b < G_CHUNKS) {
        const int g = b, s = g >> 4, r = g & 15;
        const int t0 = g * CHUNK, t1 = min(t0 + CHUNK, NTRANS);
        float v;
        {
            float vs = Vs[s*16 + lane];
            if (r == 0) v = vs;
            else {
                const float* Pm = P + (s*16 + r - 1) * 256;
                float tmp[16];
#pragma unroll
                for (int i = 0; i < 16; i++) tmp[i] = __shfl_sync(mask, vs, i) + Pm[i*16+lane];
                float mx = tmp[0];
#pragma unroll
                for (int i = 1; i < 16; i++) mx = fmaxf(mx, tmp[i]);
                float ss = 0.f;
#pragma unroll
                for (int i = 0; i < 16; i++) ss += __expf(tmp[i] - mx);
                v = mx + __logf(ss);
            }
        }
        if (g == 0) out_alpha[lane] = v;
        for (int t = t0; t < t1; t++) {
            const float* M = trs + (size_t)t * 256;
            float tmp[16];
#pragma unroll
            for (int i = 0; i < 16; i++) tmp[i] = __shfl_sync(mask, v, i) + M[i*16+lane];
            float mx = tmp[0];
#pragma unroll
            for (int i = 1; i < 16; i++) mx = fmaxf(mx, tmp[i]);
            float ss = 0.f;
#pragma unroll
            for (int i = 0; i < 16; i++) ss += __expf(tmp[i] - mx);
            v = mx + __logf(ss) + pis[(size_t)(t+1) * 16 + lane];
            out_alpha[(size_t)(t+1) * 16 + lane] = v;
        }
    } else {
        const int g = b - G_CHUNKS, s = g >> 4, r = g & 15;
        const int t0 = g * CHUNK, t1 = min(t0 + CHUNK, NTRANS);
        float w;
        {
            float wsv = Wsv[(s+1)*16 + lane];
            if (r == 15) w = wsv;
            else {
                const float* Sf = Suf + (s*16 + r + 1) * 256 + lane * 16;
                float tmp[16];
#pragma unroll
                for (int j = 0; j < 16; j++) tmp[j] = Sf[j] + __shfl_sync(mask, wsv, j);
                float mx = tmp[0];
#pragma unroll
                for (int j = 1; j < 16; j++) mx = fmaxf(mx, tmp[j]);
                float ss = 0.f;
#pragma unroll
                for (int j = 0; j < 16; j++) ss += __expf(tmp[j] - mx);
                w = mx + __logf(ss);
            }
        }
        for (int t = t1 - 1; t >= t0; t--) {
            const float* M = trs + (size_t)t * 256 + lane * 16;
            float u = w + pis[(size_t)(t+1) * 16 + lane];
            float tmp[16];
#pragma unroll
            for (int j = 0; j < 16; j++) tmp[j] = __shfl_sync(mask, u, j) + M[j];
            float mx = tmp[0];
#pragma unroll
            for (int j = 1; j < 16; j++) mx = fmaxf(mx, tmp[j]);
            float ss = 0.f;
#pragma unroll
            for (int j = 0; j < 16; j++) ss += __expf(tmp[j] - mx);
            w = mx + __logf(ss);
            out_beta[(size_t)t * 16 + lane] = w;
        }
    }
}

// ---------------- host launcher ----------------
extern "C" void kernel_launch(void* const* d_in, const int* in_sizes, int n_in,
                              void* d_out, int out_size)
{
    const float* s_arr = (const float*)d_in[0];
    const float* a_arr = (const float*)d_in[1];
    const float* pW1 = (const float*)d_in[2];  const float* pb1 = (const float*)d_in[3];
    const float* pW2 = (const float*)d_in[4];  const float* pb2 = (const float*)d_in[5];
    const float* pW3 = (const float*)d_in[6];  const float* pb3 = (const float*)d_in[7];
    const float* oW1 = (const float*)d_in[8];  const float* ob1 = (const float*)d_in[9];
    const float* oW2 = (const float*)d_in[10]; const float* ob2 = (const float*)d_in[11];
    const float* oW3 = (const float*)d_in[12]; const float* ob3 = (const float*)d_in[13];
    const float* als = (const float*)d_in[14];

    float* out = (float*)d_out;
    float* out_alpha = out + OFF_ALPHA;
    float* out_beta  = out + OFF_BETA;
    float* out_trs   = out + OFF_TRS;
    float* out_pis   = out + OFF_PIS;
    float* out_ent   = out + OFF_ENT;

    __nv_bfloat16 *sH, *sL, *h1pH, *h1pL, *h1oH, *h1oL, *h2pH, *h2pL, *h2oH, *h2oL, *wtH, *wtL;
    float *meanb, *logitsb, *Cmat, *Pm, *Sf, *Vs, *Wsv, *tr0;
    cudaGetSymbolAddress((void**)&sH, g_sH);     cudaGetSymbolAddress((void**)&sL, g_sL);
    cudaGetSymbolAddress((void**)&h1pH, g_h1pH); cudaGetSymbolAddress((void**)&h1pL, g_h1pL);
    cudaGetSymbolAddress((void**)&h1oH, g_h1oH); cudaGetSymbolAddress((void**)&h1oL, g_h1oL);
    cudaGetSymbolAddress((void**)&h2pH, g_h2pH); cudaGetSymbolAddress((void**)&h2pL, g_h2pL);
    cudaGetSymbolAddress((void**)&h2oH, g_h2oH); cudaGetSymbolAddress((void**)&h2oL, g_h2oL);
    cudaGetSymbolAddress((void**)&wtH, g_wtH);   cudaGetSymbolAddress((void**)&wtL, g_wtL);
    cudaGetSymbolAddress((void**)&meanb, g_mean);
    cudaGetSymbolAddress((void**)&logitsb, g_logits);
    cudaGetSymbolAddress((void**)&Cmat, g_Cmat);
    cudaGetSymbolAddress((void**)&Pm, g_P);
    cudaGetSymbolAddress((void**)&Sf, g_Suf);
    cudaGetSymbolAddress((void**)&Vs, g_Vs);
    cudaGetSymbolAddress((void**)&Wsv, g_Wsv);
    cudaGetSymbolAddress((void**)&tr0, g_tr0);

    cudaFuncSetAttribute(gemm6<64, 256, true, false, true>,
                         cudaFuncAttributeMaxDynamicSharedMemorySize, SMEM_DYN);
    cudaFuncSetAttribute(gemm6<256, 256, true, false, true>,
                         cudaFuncAttributeMaxDynamicSharedMemorySize, SMEM_DYN);
    cudaFuncSetAttribute(gemm6<256, 128, false, false, false>,
                         cudaFuncAttributeMaxDynamicSharedMemorySize, SMEM_DYN);
    cudaFuncSetAttribute(gemm6<256, 272, false, true, false>,
                         cudaFuncAttributeMaxDynamicSharedMemorySize, SMEM_DYN);

    prep_weights<<<(6 * WT_SZ + 255) / 256, 256>>>(pW1, oW1, pW2, oW2, pW3, oW3, wtH, wtL);
    prep_sact<<<(T_LEN * 64 + 255) / 256, 256>>>(s_arr, sH, sL);

    const int MB = T_LEN / 128;  // 512

    gemm6<64, 256, true, false, true><<<dim3(MB, 2, 2), 256, SMEM_DYN>>>(
        sH, sL, wtH + 0*WT_SZ, wtL + 0*WT_SZ, pb1, nullptr, h1pH, h1pL,
        sH, sL, wtH + 1*WT_SZ, wtL + 1*WT_SZ, ob1, nullptr, h1oH, h1oL);
    gemm6<256, 256, true, false, true><<<dim3(MB, 2, 2), 256, SMEM_DYN>>>(
        h1pH, h1pL, wtH + 2*WT_SZ, wtL + 2*WT_SZ, pb2, nullptr, h2pH, h2pL,
        h1oH, h1oL, wtH + 3*WT_SZ, wtL + 3*WT_SZ, ob2, nullptr, h2oH, h2oL);
    gemm6<256, 128, false, false, false><<<dim3(MB, 1, 1), 256, SMEM_DYN>>>(
        h2pH, h2pL, wtH + 4*WT_SZ, wtL + 4*WT_SZ, pb3, meanb, nullptr, nullptr,
        h2pH, h2pL, wtH + 4*WT_SZ, wtL + 4*WT_SZ, pb3, meanb, nullptr, nullptr);
    gemm6<256, 272, false, true, false><<<dim3(MB, 3, 1), 256, SMEM_DYN>>>(
        h2oH, h2oL, wtH + 5*WT_SZ, wtL + 5*WT_SZ, ob3, logitsb, nullptr, nullptr,
        h2oH, h2oL, wtH + 5*WT_SZ, wtL + 5*WT_SZ, ob3, logitsb, nullptr, nullptr);

    logpis_kernel<<<(T_LEN * DIM_C + 255) / 256, 256>>>(meanb, a_arr, als, out_pis);
    softmax_kernel<<<(T_LEN * 17 + 255) / 256, 256>>>(logitsb, out_trs, out_ent, tr0);

    pass1_kernel<<<G_CHUNKS, 256>>>(out_trs, out_pis, Cmat);
    superprod_kernel<<<2 * NSUPER, 256>>>(Cmat, Pm, Sf);
    combine2_kernel<<<2, 32>>>(Pm, tr0, out_pis, Vs, Wsv, out_beta);
    pass2_kernel<<<2 * G_CHUNKS, 32>>>(out_trs, out_pis, Pm, Sf, Vs, Wsv,
                                       out_alpha, out_beta);
}

// round 15
// speedup vs baseline: 1.2177x; 1.1037x over previous
#include <cuda_runtime.h>
#include <cuda_bf16.h>
#include <cfloat>
#include <math.h>
#include <stdint.h>

#define T_LEN   65536
#define DIM_A   8
#define DIM_C   16
#define NTRANS  (T_LEN - 1)
#define CHUNK   256
#define G_CHUNKS 256
#define NSUPER  16

static const size_t OFF_ALPHA = 0;
static const size_t OFF_BETA  = (size_t)T_LEN * DIM_C;
static const size_t OFF_TRS   = 2ull * T_LEN * DIM_C;
static const size_t OFF_PIS   = OFF_TRS + (size_t)NTRANS * DIM_C * DIM_C;
static const size_t OFF_ENT   = OFF_PIS + (size_t)T_LEN * DIM_C;

// ---------------- device scratch ----------------
__device__ __nv_bfloat16 g_sH [(size_t)T_LEN * 64];
__device__ __nv_bfloat16 g_sL [(size_t)T_LEN * 64];
__device__ __nv_bfloat16 g_h1pH[(size_t)T_LEN * 256];
__device__ __nv_bfloat16 g_h1pL[(size_t)T_LEN * 256];
__device__ __nv_bfloat16 g_h1oH[(size_t)T_LEN * 256];
__device__ __nv_bfloat16 g_h1oL[(size_t)T_LEN * 256];
__device__ __nv_bfloat16 g_h2pH[(size_t)T_LEN * 256];
__device__ __nv_bfloat16 g_h2pL[(size_t)T_LEN * 256];
__device__ __nv_bfloat16 g_h2oH[(size_t)T_LEN * 256];
__device__ __nv_bfloat16 g_h2oL[(size_t)T_LEN * 256];
__device__ float g_Cmat[G_CHUNKS * 256];
__device__ float g_P  [G_CHUNKS * 256];
__device__ float g_Suf[G_CHUNKS * 256];
__device__ float g_Vs[(NSUPER + 1) * 16];
__device__ float g_Wsv[(NSUPER + 1) * 16];
__device__ float g_tr0[16];

#define WT_NPAD 384
#define WT_KPAD 256
#define WT_SZ   (WT_NPAD * WT_KPAD)
__device__ __nv_bfloat16 g_wtH[6 * WT_SZ];
__device__ __nv_bfloat16 g_wtL[6 * WT_SZ];

// ---------------- helpers ----------------
__device__ __forceinline__ uint32_t s2u(const void* p) {
    uint32_t a;
    asm("{ .reg .u64 t; cvta.to.shared.u64 t, %1; cvt.u32.u64 %0, t; }" : "=r"(a) : "l"(p));
    return a;
}
__device__ __forceinline__ uint32_t pack2(__nv_bfloat16 a, __nv_bfloat16 b) {
    return (uint32_t)__bfloat16_as_ushort(a) | ((uint32_t)__bfloat16_as_ushort(b) << 16);
}
__device__ __forceinline__ void cpa16(uint32_t d, const void* s) {
    asm volatile("cp.async.cg.shared.global [%0], [%1], 16;" :: "r"(d), "l"(s) : "memory");
}
#define CP_COMMIT() asm volatile("cp.async.commit_group;" ::: "memory")
#define LDM4(r, a) \
    asm volatile("ldmatrix.sync.aligned.m8n8.x4.shared.b16 {%0,%1,%2,%3}, [%4];" \
        : "=r"((r)[0]), "=r"((r)[1]), "=r"((r)[2]), "=r"((r)[3]) : "r"(a))
__device__ __forceinline__ void mma16816(float c[4], const uint32_t a[4], const uint32_t b[2]) {
    asm volatile(
        "mma.sync.aligned.m16n8k16.row.col.f32.bf16.bf16.f32 "
        "{%0,%1,%2,%3}, {%4,%5,%6,%7}, {%8,%9}, {%0,%1,%2,%3};\n"
        : "+f"(c[0]), "+f"(c[1]), "+f"(c[2]), "+f"(c[3])
        : "r"(a[0]), "r"(a[1]), "r"(a[2]), "r"(a[3]), "r"(b[0]), "r"(b[1]));
}
#define SWZ64(o) ((o) ^ (((o) >> 3) & 0x30))

// ---------------- prep kernels ----------------
__global__ void prep_weights(const float* __restrict__ W0, const float* __restrict__ W1,
                             const float* __restrict__ W2, const float* __restrict__ W3,
                             const float* __restrict__ W4, const float* __restrict__ W5,
                             __nv_bfloat16* __restrict__ WH, __nv_bfloat16* __restrict__ WL)
{
    int idx = blockIdx.x * blockDim.x + threadIdx.x;
    if (idx >= 6 * WT_SZ) return;
    const int layer = idx / WT_SZ;
    const int rem = idx - layer * WT_SZ;
    const int n = rem >> 8, k = rem & 255;
    const int Ks[6] = {64, 64, 256, 256, 256, 256};
    const int Ns[6] = {256, 256, 256, 256, 128, 272};
    const float* Ws[6] = {W0, W1, W2, W3, W4, W5};
    float v = 0.f;
    if (n < Ns[layer] && k < Ks[layer]) v = Ws[layer][(size_t)k * Ns[layer] + n];
    __nv_bfloat16 h = __float2bfloat16(v);
    WH[idx] = h;
    WL[idx] = __float2bfloat16(v - __bfloat162float(h));
}

__global__ void prep_sact(const float* __restrict__ s,
                          __nv_bfloat16* __restrict__ H, __nv_bfloat16* __restrict__ L)
{
    int idx = blockIdx.x * blockDim.x + threadIdx.x;
    if (idx >= T_LEN * 64) return;
    float v = s[idx];
    __nv_bfloat16 h = __float2bfloat16(v);
    H[idx] = h;
    L[idx] = __float2bfloat16(v - __bfloat162float(h));
}

// ---------------- GEMM: ldmatrix + 3-stage cp.async + split-bf16 x3 mma ----------------
// EPI: 0 = split-bf16 store (hidden layers), 1 = fused log_pis, 2 = fused log_softmax.
#define STG 32768
#define SMEM_DYN (3 * STG + 1024)

template <int K, int N, bool RELU, bool NG, int EPI>
__global__ __launch_bounds__(256, 2) void gemm7(
    const __nv_bfloat16* __restrict__ AH0, const __nv_bfloat16* __restrict__ AL0,
    const __nv_bfloat16* __restrict__ WH0, const __nv_bfloat16* __restrict__ WL0,
    const float* __restrict__ b0, __nv_bfloat16* __restrict__ CH0, __nv_bfloat16* __restrict__ CL0,
    const __nv_bfloat16* __restrict__ AH1, const __nv_bfloat16* __restrict__ AL1,
    const __nv_bfloat16* __restrict__ WH1, const __nv_bfloat16* __restrict__ WL1,
    const float* __restrict__ b1, __nv_bfloat16* __restrict__ CH1, __nv_bfloat16* __restrict__ CL1,
    const float* __restrict__ a_arr, const float* __restrict__ a_ls,
    float* __restrict__ out_pis, float* __restrict__ out_trs,
    float* __restrict__ out_ent, float* __restrict__ tr0)
{
    constexpr int NSLAB = K / 32;
    const __nv_bfloat16* AH = blockIdx.z ? AH1 : AH0;
    const __nv_bfloat16* AL = blockIdx.z ? AL1 : AL0;
    const __nv_bfloat16* WH = blockIdx.z ? WH1 : WH0;
    const __nv_bfloat16* WL = blockIdx.z ? WL1 : WL0;
    const float* bias = blockIdx.z ? b1 : b0;
    __nv_bfloat16* CH = blockIdx.z ? CH1 : CH0;
    __nv_bfloat16* CL = blockIdx.z ? CL1 : CL0;

    extern __shared__ uint8_t dsm[];
    const uint32_t smb = (s2u(dsm) + 1023u) & ~1023u;

    const int tid = threadIdx.x, lane = tid & 31, wid = tid >> 5;
    const int warpM = (wid & 1) * 64, warpN = (wid >> 1) * 32;
    const int row0 = blockIdx.x * 128, col0 = blockIdx.y * 128;

    const int m = tid >> 1, half = tid & 1;
    const __nv_bfloat16* pAH = AH + (size_t)(row0 + m) * K + half * 16;
    const __nv_bfloat16* pAL = AL + (size_t)(row0 + m) * K + half * 16;
    const __nv_bfloat16* pWH = WH + (size_t)(col0 + m) * WT_KPAD + half * 16;
    const __nv_bfloat16* pWL = WL + (size_t)(col0 + m) * WT_KPAD + half * 16;
    const uint32_t dsw0 = SWZ64((uint32_t)(m * 64 + half * 32));
    const uint32_t dsw1 = SWZ64((uint32_t)(m * 64 + half * 32 + 16));

    auto issue = [&](int s, int st) {
        const uint32_t SB = smb + st * STG;
        cpa16(SB + dsw0,         pAH + s * 32);
        cpa16(SB + dsw1,         pAH + s * 32 + 8);
        cpa16(SB + 8192  + dsw0, pAL + s * 32);
        cpa16(SB + 8192  + dsw1, pAL + s * 32 + 8);
        cpa16(SB + 16384 + dsw0, pWH + s * 32);
        cpa16(SB + 16384 + dsw1, pWH + s * 32 + 8);
        cpa16(SB + 24576 + dsw0, pWL + s * 32);
        cpa16(SB + 24576 + dsw1, pWL + s * 32 + 8);
        CP_COMMIT();
    };

    float acc[4][4][4];
#pragma unroll
    for (int mt = 0; mt < 4; mt++)
#pragma unroll
        for (int nt = 0; nt < 4; nt++)
#pragma unroll
            for (int q = 0; q < 4; q++) acc[mt][nt][q] = 0.f;

    const int mat = lane >> 3, rin = lane & 7;
    const int a_row = warpM + ((mat & 1) << 3) + rin;
    const int a_kb  = (mat >> 1) << 4;
    const int b_row = warpN + ((mat >> 1) << 3) + rin;
    const int b_kb  = (mat & 1) << 4;

    auto compute = [&](int st) {
        const uint32_t SB = smb + st * STG;
#pragma unroll
        for (int ks = 0; ks < 2; ks++) {
            uint32_t bh[2][4], bl[2][4];
#pragma unroll
            for (int p = 0; p < 2; p++) {
                uint32_t sw = SWZ64((uint32_t)((b_row + p * 16) * 64 + ks * 32 + b_kb));
                LDM4(bh[p], SB + 16384 + sw);
                LDM4(bl[p], SB + 24576 + sw);
            }
#pragma unroll
            for (int mt = 0; mt < 4; mt++) {
                uint32_t sw = SWZ64((uint32_t)((a_row + mt * 16) * 64 + ks * 32 + a_kb));
                uint32_t ah[4], al[4];
                LDM4(ah, SB + sw);
                LDM4(al, SB + 8192 + sw);
#pragma unroll
                for (int nt = 0; nt < 4; nt++) {
                    const int p = nt >> 1, ix = (nt & 1) * 2;
                    uint32_t bbh[2] = {bh[p][ix], bh[p][ix + 1]};
                    uint32_t bbl[2] = {bl[p][ix], bl[p][ix + 1]};
                    mma16816(acc[mt][nt], ah, bbh);
                    mma16816(acc[mt][nt], ah, bbl);
                    mma16816(acc[mt][nt], al, bbh);
                }
            }
        }
    };

    // 3-stage pipeline, single sync per slab
    issue(0, 0);
    if (NSLAB > 1) issue(1, 1);
#pragma unroll 1
    for (int s = 0; s < NSLAB; s++) {
        if (s < NSLAB - 1) asm volatile("cp.async.wait_group 1;" ::: "memory");
        else               asm volatile("cp.async.wait_group 0;" ::: "memory");
        __syncthreads();
        compute(s % 3);
        if (s + 2 < NSLAB) issue(s + 2, (s + 2) % 3);
    }

    const int g = lane >> 2, c = lane & 3;

    if constexpr (EPI == 0) {
#pragma unroll
        for (int mt = 0; mt < 4; mt++) {
#pragma unroll
            for (int nt = 0; nt < 4; nt++) {
                const int col = col0 + warpN + nt * 8 + c * 2;
                const float bx = bias[col], by = bias[col + 1];
                const int rw = row0 + warpM + mt * 16 + g;
                float v0 = acc[mt][nt][0] + bx, v1 = acc[mt][nt][1] + by;
                float v2 = acc[mt][nt][2] + bx, v3 = acc[mt][nt][3] + by;
                if (RELU) {
                    v0 = fmaxf(v0, 0.f); v1 = fmaxf(v1, 0.f);
                    v2 = fmaxf(v2, 0.f); v3 = fmaxf(v3, 0.f);
                }
                __nv_bfloat16 h0 = __float2bfloat16(v0), h1 = __float2bfloat16(v1);
                __nv_bfloat16 h2 = __float2bfloat16(v2), h3 = __float2bfloat16(v3);
                *(uint32_t*)&CH[(size_t)rw * N + col] = pack2(h0, h1);
                *(uint32_t*)&CL[(size_t)rw * N + col] =
                    pack2(__float2bfloat16(v0 - __bfloat162float(h0)),
                          __float2bfloat16(v1 - __bfloat162float(h1)));
                *(uint32_t*)&CH[(size_t)(rw + 8) * N + col] = pack2(h2, h3);
                *(uint32_t*)&CL[(size_t)(rw + 8) * N + col] =
                    pack2(__float2bfloat16(v2 - __bfloat162float(h2)),
                          __float2bfloat16(v3 - __bfloat162float(h3)));
            }
        }
    }

    if constexpr (EPI == 1) {   // fused log_pis (N = 128, col0 = 0)
        float lsv[8]; float lsum = 0.f;
#pragma unroll
        for (int a = 0; a < 8; a++) {
            float l = tanhf(a_ls[a]);
            l = -5.0f + 3.5f * (l + 1.0f);
            lsv[a] = l; lsum += l;
        }
        const float cst = -lsum - 4.0f * 1.8378770664093453f;
        const float is0 = expf(-lsv[c * 2]), is1 = expf(-lsv[c * 2 + 1]);
#pragma unroll
        for (int mt = 0; mt < 4; mt++) {
            const int rw = row0 + warpM + mt * 16 + g;
            const float a00 = a_arr[(size_t)rw * 8 + c * 2];
            const float a01 = a_arr[(size_t)rw * 8 + c * 2 + 1];
            const float a10 = a_arr[(size_t)(rw + 8) * 8 + c * 2];
            const float a11 = a_arr[(size_t)(rw + 8) * 8 + c * 2 + 1];
#pragma unroll
            for (int nt = 0; nt < 4; nt++) {
                const int col = warpN + nt * 8 + c * 2;
                const float bx = bias[col], by = bias[col + 1];
                const int cc = (warpN >> 3) + nt;
                float m00 = fminf(fmaxf(acc[mt][nt][0] + bx, -10.f), 10.f);
                float m01 = fminf(fmaxf(acc[mt][nt][1] + by, -10.f), 10.f);
                float m10 = fminf(fmaxf(acc[mt][nt][2] + bx, -10.f), 10.f);
                float m11 = fminf(fmaxf(acc[mt][nt][3] + by, -10.f), 10.f);
                float z, s0, s1;
                z = (a00 - m00) * is0; s0 = z * z;
                z = (a01 - m01) * is1; s0 = fmaf(z, z, s0);
                z = (a10 - m10) * is0; s1 = z * z;
                z = (a11 - m11) * is1; s1 = fmaf(z, z, s1);
                s0 += __shfl_xor_sync(0xffffffffu, s0, 1);
                s0 += __shfl_xor_sync(0xffffffffu, s0, 2);
                s1 += __shfl_xor_sync(0xffffffffu, s1, 1);
                s1 += __shfl_xor_sync(0xffffffffu, s1, 2);
                if (c == 0) {
                    out_pis[(size_t)rw * 16 + cc]       = -0.5f * s0 + cst;
                    out_pis[(size_t)(rw + 8) * 16 + cc] = -0.5f * s1 + cst;
                }
            }
        }
    }

    if constexpr (EPI == 2) {   // fused log_softmax + entropy + tr0 (N = 272)
#pragma unroll
        for (int mt = 0; mt < 4; mt++) {
            const int rw = row0 + warpM + mt * 16 + g;
#pragma unroll
            for (int ntp = 0; ntp < 2; ntp++) {
                const int base = col0 + warpN + ntp * 16;
                if (NG && base >= N) continue;
                const int n0 = ntp * 2, n1 = ntp * 2 + 1;
                const int cA = base + c * 2, cB = base + 8 + c * 2;
                const float bv0 = bias[cA], bv1 = bias[cA + 1];
                const float bv2 = bias[cB], bv3 = bias[cB + 1];
                float v[2][4];
                v[0][0] = acc[mt][n0][0] + bv0; v[0][1] = acc[mt][n0][1] + bv1;
                v[0][2] = acc[mt][n1][0] + bv2; v[0][3] = acc[mt][n1][1] + bv3;
                v[1][0] = acc[mt][n0][2] + bv0; v[1][1] = acc[mt][n0][3] + bv1;
                v[1][2] = acc[mt][n1][2] + bv2; v[1][3] = acc[mt][n1][3] + bv3;
                const int gi = base >> 4;
#pragma unroll
                for (int r = 0; r < 2; r++) {
                    const int row = rw + r * 8;
                    float mx = fmaxf(fmaxf(v[r][0], v[r][1]), fmaxf(v[r][2], v[r][3]));
                    mx = fmaxf(mx, __shfl_xor_sync(0xffffffffu, mx, 1));
                    mx = fmaxf(mx, __shfl_xor_sync(0xffffffffu, mx, 2));
                    float s = 0.f, ws = 0.f;
#pragma unroll
                    for (int q = 0; q < 4; q++) {
                        float d = v[r][q] - mx;
                        float e = __expf(d);
                        s += e; ws = fmaf(d, e, ws);
                    }
                    s  += __shfl_xor_sync(0xffffffffu, s, 1);
                    s  += __shfl_xor_sync(0xffffffffu, s, 2);
                    ws += __shfl_xor_sync(0xffffffffu, ws, 1);
                    ws += __shfl_xor_sync(0xffffffffu, ws, 2);
                    const float ls = __logf(s), lse = mx + ls;
                    if (gi < 16) {
                        if (row >= 1) {
                            float* o = out_trs + (size_t)(row - 1) * 256 + gi * 16;
                            *(float2*)&o[c * 2]     = make_float2(v[r][0] - lse, v[r][1] - lse);
                            *(float2*)&o[8 + c * 2] = make_float2(v[r][2] - lse, v[r][3] - lse);
                            if (c == 0) out_ent[(size_t)(row - 1) * 16 + gi] = ls - ws / s;
                        }
                    } else if (row == 0) {
                        tr0[c * 2]     = v[r][0] - lse;
                        tr0[c * 2 + 1] = v[r][1] - lse;
                        tr0[8 + c * 2]     = v[r][2] - lse;
                        tr0[8 + c * 2 + 1] = v[r][3] - lse;
                    }
                }
            }
        }
    }
}

// ---------------- scan pass 1 ----------------
__global__ __launch_bounds__(256) void pass1_kernel(
    const float* __restrict__ trs, const float* __restrict__ pis, float* __restrict__ Cmat)
{
    const int g = blockIdx.x, tid = threadIdx.x;
    const int i = tid >> 4, j = tid & 15;
    const int t0 = g * CHUNK, t1 = min(t0 + CHUNK, NTRANS);
    __shared__ float Cs[2][256], Ms[256];
    Cs[0][tid] = trs[(size_t)t0 * 256 + tid] + pis[(size_t)(t0+1) * 16 + j];
    int cb = 0;
    for (int t = t0 + 1; t < t1; t++) {
        float mv = trs[(size_t)t * 256 + tid] + pis[(size_t)(t+1) * 16 + j];
        __syncthreads();
        Ms[tid] = mv;
        __syncthreads();
        float tmp[16], mx = -FLT_MAX;
#pragma unroll
        for (int k = 0; k < 16; k++) { tmp[k] = Cs[cb][i*16+k] + Ms[k*16+j]; mx = fmaxf(mx, tmp[k]); }
        float s = 0.f;
#pragma unroll
        for (int k = 0; k < 16; k++) s += __expf(tmp[k] - mx);
        Cs[cb^1][tid] = mx + __logf(s);
        cb ^= 1;
    }
    __syncthreads();
    Cmat[g * 256 + tid] = Cs[cb][tid];
}

// ---------------- group prefix/suffix products ----------------
__global__ __launch_bounds__(256) void superprod_kernel(
    const float* __restrict__ Cmat, float* __restrict__ P, float* __restrict__ Suf)
{
    const int s = blockIdx.x & 15, dir = blockIdx.x >> 4, tid = threadIdx.x;
    const int i = tid >> 4, j = tid & 15;
    __shared__ float Cs[2][256], Ms[256];
    int cb = 0;
    if (dir == 0) {
        Cs[0][tid] = Cmat[(s*16) * 256 + tid];
        P[(s*16) * 256 + tid] = Cs[0][tid];
        for (int r = 1; r < 16; r++) {
            float mv = Cmat[(s*16+r) * 256 + tid];
            __syncthreads(); Ms[tid] = mv; __syncthreads();
            float tmp[16], mx = -FLT_MAX;
#pragma unroll
            for (int k = 0; k < 16; k++) { tmp[k] = Cs[cb][i*16+k] + Ms[k*16+j]; mx = fmaxf(mx, tmp[k]); }
            float ss = 0.f;
#pragma unroll
            for (int k = 0; k < 16; k++) ss += __expf(tmp[k] - mx);
            float res = mx + __logf(ss);
            Cs[cb^1][tid] = res;
            P[(s*16+r) * 256 + tid] = res;
            cb ^= 1;
        }
    } else {
        Cs[0][tid] = Cmat[(s*16+15) * 256 + tid];
        Suf[(s*16+15) * 256 + tid] = Cs[0][tid];
        for (int r = 14; r >= 0; r--) {
            float mv = Cmat[(s*16+r) * 256 + tid];
            __syncthreads(); Ms[tid] = mv; __syncthreads();
            float tmp[16], mx = -FLT_MAX;
#pragma unroll
            for (int k = 0; k < 16; k++) { tmp[k] = Ms[i*16+k] + Cs[cb][k*16+j]; mx = fmaxf(mx, tmp[k]); }
            float ss = 0.f;
#pragma unroll
            for (int k = 0; k < 16; k++) ss += __expf(tmp[k] - mx);
            float res = mx + __logf(ss);
            Cs[cb^1][tid] = res;
            Suf[(s*16+r) * 256 + tid] = res;
            cb ^= 1;
        }
    }
}

// ---------------- serial combine ----------------
__global__ void combine2_kernel(const float* __restrict__ P, const float* __restrict__ tr0,
                                const float* __restrict__ pis, float* __restrict__ Vs,
                                float* __restrict__ Wsv, float* __restrict__ out_beta)
{
    const int lane = threadIdx.x;
    if (lane >= 16) return;
    const unsigned mask = 0xFFFFu;
    if (blockIdx.x == 0) {
        float v = tr0[lane] + pis[lane];
        Vs[lane] = v;
        for (int s = 0; s < NSUPER; s++) {
            const float* S = P + (s*16+15) * 256;
            float tmp[16];
#pragma unroll
            for (int i = 0; i < 16; i++) tmp[i] = __shfl_sync(mask, v, i) + S[i*16+lane];
            float mx = tmp[0];
#pragma unroll
            for (int i = 1; i < 16; i++) mx = fmaxf(mx, tmp[i]);
            float ss = 0.f;
#pragma unroll
            for (int i = 0; i < 16; i++) ss += __expf(tmp[i] - mx);
            v = mx + __logf(ss);
            Vs[(s+1)*16 + lane] = v;
        }
    } else {
        float w = 0.f;
        Wsv[NSUPER*16 + lane] = 0.f;
        out_beta[(size_t)(T_LEN-1) * 16 + lane] = 0.f;
        for (int s = NSUPER - 1; s >= 0; s--) {
            const float* S = P + (s*16+15) * 256 + lane * 16;
            float tmp[16];
#pragma unroll
            for (int j = 0; j < 16; j++) tmp[j] = __shfl_sync(mask, w, j) + S[j];
            float mx = tmp[0];
#pragma unroll
            for (int j = 1; j < 16; j++) mx = fmaxf(mx, tmp[j]);
            float ss = 0.f;
#pragma unroll
            for (int j = 0; j < 16; j++) ss += __expf(tmp[j] - mx);
            w = mx + __logf(ss);
            Wsv[s*16 + lane] = w;
        }
    }
}

// ---------------- scan pass 2 ----------------
__global__ void pass2_kernel(const float* __restrict__ trs, const float* __restrict__ pis,
                             const float* __restrict__ P, const float* __restrict__ Suf,
                             const float* __restrict__ Vs, const float* __restrict__ Wsv,
                             float* __restrict__ out_alpha, float* __restrict__ out_beta)
{
    const int lane = threadIdx.x;
    if (lane >= 16) return;
    const unsigned mask = 0xFFFFu;
    const int b = blockIdx.x;
    if (b < G_CHUNKS) {
        const int g = b, s = g >> 4, r = g & 15;
        const int t0 = g * CHUNK, t1 = min(t0 + CHUNK, NTRANS);
        float v;
        {
            float vs = Vs[s*16 + lane];
            if (r == 0) v = vs;
            else {
                const float* Pm = P + (s*16 + r - 1) * 256;
                float tmp[16];
#pragma unroll
                for (int i = 0; i < 16; i++) tmp[i] = __shfl_sync(mask, vs, i) + Pm[i*16+lane];
                float mx = tmp[0];
#pragma unroll
                for (int i = 1; i < 16; i++) mx = fmaxf(mx, tmp[i]);
                float ss = 0.f;
#pragma unroll
                for (int i = 0; i < 16; i++) ss += __expf(tmp[i] - mx);
                v = mx + __logf(ss);
            }
        }
        if (g == 0) out_alpha[lane] = v;
        for (int t = t0; t < t1; t++) {
            const float* M = trs + (size_t)t * 256;
            float tmp[16];
#pragma unroll
            for (int i = 0; i < 16; i++) tmp[i] = __shfl_sync(mask, v, i) + M[i*16+lane];
            float mx = tmp[0];
#pragma unroll
            for (int i = 1; i < 16; i++) mx = fmaxf(mx, tmp[i]);
            float ss = 0.f;
#pragma unroll
            for (int i = 0; i < 16; i++) ss += __expf(tmp[i] - mx);
            v = mx + __logf(ss) + pis[(size_t)(t+1) * 16 + lane];
            out_alpha[(size_t)(t+1) * 16 + lane] = v;
        }
    } else {
        const int g = b - G_CHUNKS, s = g >> 4, r = g & 15;
        const int t0 = g * CHUNK, t1 = min(t0 + CHUNK, NTRANS);
        float w;
        {
            float wsv = Wsv[(s+1)*16 + lane];
            if (r == 15) w = wsv;
            else {
                const float* Sf = Suf + (s*16 + r + 1) * 256 + lane * 16;
                float tmp[16];
#pragma unroll
                for (int j = 0; j < 16; j++) tmp[j] = Sf[j] + __shfl_sync(mask, wsv, j);
                float mx = tmp[0];
#pragma unroll
                for (int j = 1; j < 16; j++) mx = fmaxf(mx, tmp[j]);
                float ss = 0.f;
#pragma unroll
                for (int j = 0; j < 16; j++) ss += __expf(tmp[j] - mx);
                w = mx + __logf(ss);
            }
        }
        for (int t = t1 - 1; t >= t0; t--) {
            const float* M = trs + (size_t)t * 256 + lane * 16;
            float u = w + pis[(size_t)(t+1) * 16 + lane];
            float tmp[16];
#pragma unroll
            for (int j = 0; j < 16; j++) tmp[j] = __shfl_sync(mask, u, j) + M[j];
            float mx = tmp[0];
#pragma unroll
            for (int j = 1; j < 16; j++) mx = fmaxf(mx, tmp[j]);
            float ss = 0.f;
#pragma unroll
            for (int j = 0; j < 16; j++) ss += __expf(tmp[j] - mx);
            w = mx + __logf(ss);
            out_beta[(size_t)t * 16 + lane] = w;
        }
    }
}

// ---------------- host launcher ----------------
extern "C" void kernel_launch(void* const* d_in, const int* in_sizes, int n_in,
                              void* d_out, int out_size)
{
    const float* s_arr = (const float*)d_in[0];
    const float* a_arr = (const float*)d_in[1];
    const float* pW1 = (const float*)d_in[2];  const float* pb1 = (const float*)d_in[3];
    const float* pW2 = (const float*)d_in[4];  const float* pb2 = (const float*)d_in[5];
    const float* pW3 = (const float*)d_in[6];  const float* pb3 = (const float*)d_in[7];
    const float* oW1 = (const float*)d_in[8];  const float* ob1 = (const float*)d_in[9];
    const float* oW2 = (const float*)d_in[10]; const float* ob2 = (const float*)d_in[11];
    const float* oW3 = (const float*)d_in[12]; const float* ob3 = (const float*)d_in[13];
    const float* als = (const float*)d_in[14];

    float* out = (float*)d_out;
    float* out_alpha = out + OFF_ALPHA;
    float* out_beta  = out + OFF_BETA;
    float* out_trs   = out + OFF_TRS;
    float* out_pis   = out + OFF_PIS;
    float* out_ent   = out + OFF_ENT;

    __nv_bfloat16 *sH, *sL, *h1pH, *h1pL, *h1oH, *h1oL, *h2pH, *h2pL, *h2oH, *h2oL, *wtH, *wtL;
    float *Cmat, *Pm, *Sf, *Vs, *Wsv, *tr0;
    cudaGetSymbolAddress((void**)&sH, g_sH);     cudaGetSymbolAddress((void**)&sL, g_sL);
    cudaGetSymbolAddress((void**)&h1pH, g_h1pH); cudaGetSymbolAddress((void**)&h1pL, g_h1pL);
    cudaGetSymbolAddress((void**)&h1oH, g_h1oH); cudaGetSymbolAddress((void**)&h1oL, g_h1oL);
    cudaGetSymbolAddress((void**)&h2pH, g_h2pH); cudaGetSymbolAddress((void**)&h2pL, g_h2pL);
    cudaGetSymbolAddress((void**)&h2oH, g_h2oH); cudaGetSymbolAddress((void**)&h2oL, g_h2oL);
    cudaGetSymbolAddress((void**)&wtH, g_wtH);   cudaGetSymbolAddress((void**)&wtL, g_wtL);
    cudaGetSymbolAddress((void**)&Cmat, g_Cmat);
    cudaGetSymbolAddress((void**)&Pm, g_P);
    cudaGetSymbolAddress((void**)&Sf, g_Suf);
    cudaGetSymbolAddress((void**)&Vs, g_Vs);
    cudaGetSymbolAddress((void**)&Wsv, g_Wsv);
    cudaGetSymbolAddress((void**)&tr0, g_tr0);

    cudaFuncSetAttribute(gemm7<64, 256, true, false, 0>,
                         cudaFuncAttributeMaxDynamicSharedMemorySize, SMEM_DYN);
    cudaFuncSetAttribute(gemm7<256, 256, true, false, 0>,
                         cudaFuncAttributeMaxDynamicSharedMemorySize, SMEM_DYN);
    cudaFuncSetAttribute(gemm7<256, 128, false, false, 1>,
                         cudaFuncAttributeMaxDynamicSharedMemorySize, SMEM_DYN);
    cudaFuncSetAttribute(gemm7<256, 272, false, true, 2>,
                         cudaFuncAttributeMaxDynamicSharedMemorySize, SMEM_DYN);

    prep_weights<<<(6 * WT_SZ + 255) / 256, 256>>>(pW1, oW1, pW2, oW2, pW3, oW3, wtH, wtL);
    prep_sact<<<(T_LEN * 64 + 255) / 256, 256>>>(s_arr, sH, sL);

    const int MB = T_LEN / 128;  // 512

    gemm7<64, 256, true, false, 0><<<dim3(MB, 2, 2), 256, SMEM_DYN>>>(
        sH, sL, wtH + 0*WT_SZ, wtL + 0*WT_SZ, pb1, h1pH, h1pL,
        sH, sL, wtH + 1*WT_SZ, wtL + 1*WT_SZ, ob1, h1oH, h1oL,
        nullptr, nullptr, nullptr, nullptr, nullptr, nullptr);
    gemm7<256, 256, true, false, 0><<<dim3(MB, 2, 2), 256, SMEM_DYN>>>(
        h1pH, h1pL, wtH + 2*WT_SZ, wtL + 2*WT_SZ, pb2, h2pH, h2pL,
        h1oH, h1oL, wtH + 3*WT_SZ, wtL + 3*WT_SZ, ob2, h2oH, h2oL,
        nullptr, nullptr, nullptr, nullptr, nullptr, nullptr);
    gemm7<256, 128, false, false, 1><<<dim3(MB, 1, 1), 256, SMEM_DYN>>>(
        h2pH, h2pL, wtH + 4*WT_SZ, wtL + 4*WT_SZ, pb3, nullptr, nullptr,
        h2pH, h2pL, wtH + 4*WT_SZ, wtL + 4*WT_SZ, pb3, nullptr, nullptr,
        a_arr, als, out_pis, nullptr, nullptr, nullptr);
    gemm7<256, 272, false, true, 2><<<dim3(MB, 3, 1), 256, SMEM_DYN>>>(
        h2oH, h2oL, wtH + 5*WT_SZ, wtL + 5*WT_SZ, ob3, nullptr, nullptr,
        h2oH, h2oL, wtH + 5*WT_SZ, wtL + 5*WT_SZ, ob3, nullptr, nullptr,
        nullptr, nullptr, nullptr, out_trs, out_ent, tr0);

    pass1_kernel<<<G_CHUNKS, 256>>>(out_trs, out_pis, Cmat);
    superprod_kernel<<<2 * NSUPER, 256>>>(Cmat, Pm, Sf);
    combine2_kernel<<<2, 32>>>(Pm, tr0, out_pis, Vs, Wsv, out_beta);
    pass2_kernel<<<2 * G_CHUNKS, 32>>>(out_trs, out_pis, Pm, Sf, Vs, Wsv,
                                       out_alpha, out_beta);
}

// round 16
// speedup vs baseline: 1.2264x; 1.0071x over previous
#include <cuda_runtime.h>
#include <cuda_bf16.h>
#include <cfloat>
#include <math.h>
#include <stdint.h>

#define T_LEN   65536
#define DIM_A   8
#define DIM_C   16
#define NTRANS  (T_LEN - 1)
#define CHUNK   256
#define G_CHUNKS 256
#define NSUPER  16

static const size_t OFF_ALPHA = 0;
static const size_t OFF_BETA  = (size_t)T_LEN * DIM_C;
static const size_t OFF_TRS   = 2ull * T_LEN * DIM_C;
static const size_t OFF_PIS   = OFF_TRS + (size_t)NTRANS * DIM_C * DIM_C;
static const size_t OFF_ENT   = OFF_PIS + (size_t)T_LEN * DIM_C;

// ---------------- device scratch ----------------
__device__ __nv_bfloat16 g_sH [(size_t)T_LEN * 64];
__device__ __nv_bfloat16 g_sL [(size_t)T_LEN * 64];
__device__ __nv_bfloat16 g_h1pH[(size_t)T_LEN * 256];
__device__ __nv_bfloat16 g_h1pL[(size_t)T_LEN * 256];
__device__ __nv_bfloat16 g_h1oH[(size_t)T_LEN * 256];
__device__ __nv_bfloat16 g_h1oL[(size_t)T_LEN * 256];
__device__ __nv_bfloat16 g_h2pH[(size_t)T_LEN * 256];
__device__ __nv_bfloat16 g_h2pL[(size_t)T_LEN * 256];
__device__ __nv_bfloat16 g_h2oH[(size_t)T_LEN * 256];
__device__ __nv_bfloat16 g_h2oL[(size_t)T_LEN * 256];
__device__ float g_Cmat[G_CHUNKS * 256];
__device__ float g_P  [G_CHUNKS * 256];
__device__ float g_Suf[G_CHUNKS * 256];
__device__ float g_Vs[(NSUPER + 1) * 16];
__device__ float g_Wsv[(NSUPER + 1) * 16];
__device__ float g_tr0[16];

#define WT_NPAD 384
#define WT_KPAD 256
#define WT_SZ   (WT_NPAD * WT_KPAD)
__device__ __nv_bfloat16 g_wtH[6 * WT_SZ];
__device__ __nv_bfloat16 g_wtL[6 * WT_SZ];

// ---------------- helpers ----------------
__device__ __forceinline__ uint32_t s2u(const void* p) {
    uint32_t a;
    asm("{ .reg .u64 t; cvta.to.shared.u64 t, %1; cvt.u32.u64 %0, t; }" : "=r"(a) : "l"(p));
    return a;
}
__device__ __forceinline__ uint32_t pack2(__nv_bfloat16 a, __nv_bfloat16 b) {
    return (uint32_t)__bfloat16_as_ushort(a) | ((uint32_t)__bfloat16_as_ushort(b) << 16);
}
__device__ __forceinline__ void cpa16(uint32_t d, const void* s) {
    asm volatile("cp.async.cg.shared.global [%0], [%1], 16;" :: "r"(d), "l"(s) : "memory");
}
#define CP_COMMIT() asm volatile("cp.async.commit_group;" ::: "memory")
#define LDM4(r, a) \
    asm volatile("ldmatrix.sync.aligned.m8n8.x4.shared.b16 {%0,%1,%2,%3}, [%4];" \
        : "=r"((r)[0]), "=r"((r)[1]), "=r"((r)[2]), "=r"((r)[3]) : "r"(a))
__device__ __forceinline__ void mma16816(float c[4], const uint32_t a[4], const uint32_t b[2]) {
    asm volatile(
        "mma.sync.aligned.m16n8k16.row.col.f32.bf16.bf16.f32 "
        "{%0,%1,%2,%3}, {%4,%5,%6,%7}, {%8,%9}, {%0,%1,%2,%3};\n"
        : "+f"(c[0]), "+f"(c[1]), "+f"(c[2]), "+f"(c[3])
        : "r"(a[0]), "r"(a[1]), "r"(a[2]), "r"(a[3]), "r"(b[0]), "r"(b[1]));
}
#define SWZ64(o) ((o) ^ (((o) >> 3) & 0x30))

// ---------------- prep kernels ----------------
__global__ void prep_weights(const float* __restrict__ W0, const float* __restrict__ W1,
                             const float* __restrict__ W2, const float* __restrict__ W3,
                             const float* __restrict__ W4, const float* __restrict__ W5,
                             __nv_bfloat16* __restrict__ WH, __nv_bfloat16* __restrict__ WL)
{
    int idx = blockIdx.x * blockDim.x + threadIdx.x;
    if (idx >= 6 * WT_SZ) return;
    const int layer = idx / WT_SZ;
    const int rem = idx - layer * WT_SZ;
    const int n = rem >> 8, k = rem & 255;
    const int Ks[6] = {64, 64, 256, 256, 256, 256};
    const int Ns[6] = {256, 256, 256, 256, 128, 272};
    const float* Ws[6] = {W0, W1, W2, W3, W4, W5};
    float v = 0.f;
    if (n < Ns[layer] && k < Ks[layer]) v = Ws[layer][(size_t)k * Ns[layer] + n];
    __nv_bfloat16 h = __float2bfloat16(v);
    WH[idx] = h;
    WL[idx] = __float2bfloat16(v - __bfloat162float(h));
}

__global__ void prep_sact(const float* __restrict__ s,
                          __nv_bfloat16* __restrict__ H, __nv_bfloat16* __restrict__ L)
{
    int idx = blockIdx.x * blockDim.x + threadIdx.x;
    if (idx >= T_LEN * 64) return;
    float v = s[idx];
    __nv_bfloat16 h = __float2bfloat16(v);
    H[idx] = h;
    L[idx] = __float2bfloat16(v - __bfloat162float(h));
}

// ---------------- GEMM: ldmatrix + 3-stage cp.async + split-bf16 x3 mma ----------------
// EPI: 0 = split-bf16 store (hidden layers), 1 = fused log_pis, 2 = fused log_softmax.
#define STG 32768
#define SMEM_DYN (3 * STG + 1024)

template <int K, int N, bool RELU, bool NG, int EPI>
__global__ __launch_bounds__(256, 2) void gemm7(
    const __nv_bfloat16* __restrict__ AH0, const __nv_bfloat16* __restrict__ AL0,
    const __nv_bfloat16* __restrict__ WH0, const __nv_bfloat16* __restrict__ WL0,
    const float* __restrict__ b0, __nv_bfloat16* __restrict__ CH0, __nv_bfloat16* __restrict__ CL0,
    const __nv_bfloat16* __restrict__ AH1, const __nv_bfloat16* __restrict__ AL1,
    const __nv_bfloat16* __restrict__ WH1, const __nv_bfloat16* __restrict__ WL1,
    const float* __restrict__ b1, __nv_bfloat16* __restrict__ CH1, __nv_bfloat16* __restrict__ CL1,
    const float* __restrict__ a_arr, const float* __restrict__ a_ls,
    float* __restrict__ out_pis, float* __restrict__ out_trs,
    float* __restrict__ out_ent, float* __restrict__ tr0)
{
    constexpr int NSLAB = K / 32;
    const __nv_bfloat16* AH = blockIdx.z ? AH1 : AH0;
    const __nv_bfloat16* AL = blockIdx.z ? AL1 : AL0;
    const __nv_bfloat16* WH = blockIdx.z ? WH1 : WH0;
    const __nv_bfloat16* WL = blockIdx.z ? WL1 : WL0;
    const float* bias = blockIdx.z ? b1 : b0;
    __nv_bfloat16* CH = blockIdx.z ? CH1 : CH0;
    __nv_bfloat16* CL = blockIdx.z ? CL1 : CL0;

    extern __shared__ uint8_t dsm[];
    const uint32_t smb = (s2u(dsm) + 1023u) & ~1023u;

    const int tid = threadIdx.x, lane = tid & 31, wid = tid >> 5;
    const int warpM = (wid & 1) * 64, warpN = (wid >> 1) * 32;
    const int row0 = blockIdx.x * 128, col0 = blockIdx.y * 128;

    const int m = tid >> 1, half = tid & 1;
    const __nv_bfloat16* pAH = AH + (size_t)(row0 + m) * K + half * 16;
    const __nv_bfloat16* pAL = AL + (size_t)(row0 + m) * K + half * 16;
    const __nv_bfloat16* pWH = WH + (size_t)(col0 + m) * WT_KPAD + half * 16;
    const __nv_bfloat16* pWL = WL + (size_t)(col0 + m) * WT_KPAD + half * 16;
    const uint32_t dsw0 = SWZ64((uint32_t)(m * 64 + half * 32));
    const uint32_t dsw1 = SWZ64((uint32_t)(m * 64 + half * 32 + 16));

    auto issue = [&](int s, int st) {
        const uint32_t SB = smb + st * STG;
        cpa16(SB + dsw0,         pAH + s * 32);
        cpa16(SB + dsw1,         pAH + s * 32 + 8);
        cpa16(SB + 8192  + dsw0, pAL + s * 32);
        cpa16(SB + 8192  + dsw1, pAL + s * 32 + 8);
        cpa16(SB + 16384 + dsw0, pWH + s * 32);
        cpa16(SB + 16384 + dsw1, pWH + s * 32 + 8);
        cpa16(SB + 24576 + dsw0, pWL + s * 32);
        cpa16(SB + 24576 + dsw1, pWL + s * 32 + 8);
        CP_COMMIT();
    };

    float acc[4][4][4];
#pragma unroll
    for (int mt = 0; mt < 4; mt++)
#pragma unroll
        for (int nt = 0; nt < 4; nt++)
#pragma unroll
            for (int q = 0; q < 4; q++) acc[mt][nt][q] = 0.f;

    const int mat = lane >> 3, rin = lane & 7;
    const int a_row = warpM + ((mat & 1) << 3) + rin;
    const int a_kb  = (mat >> 1) << 4;
    const int b_row = warpN + ((mat >> 1) << 3) + rin;
    const int b_kb  = (mat & 1) << 4;

    auto compute = [&](int st) {
        const uint32_t SB = smb + st * STG;
#pragma unroll
        for (int ks = 0; ks < 2; ks++) {
            uint32_t bh[2][4], bl[2][4];
#pragma unroll
            for (int p = 0; p < 2; p++) {
                uint32_t sw = SWZ64((uint32_t)((b_row + p * 16) * 64 + ks * 32 + b_kb));
                LDM4(bh[p], SB + 16384 + sw);
                LDM4(bl[p], SB + 24576 + sw);
            }
#pragma unroll
            for (int mt = 0; mt < 4; mt++) {
                uint32_t sw = SWZ64((uint32_t)((a_row + mt * 16) * 64 + ks * 32 + a_kb));
                uint32_t ah[4], al[4];
                LDM4(ah, SB + sw);
                LDM4(al, SB + 8192 + sw);
#pragma unroll
                for (int nt = 0; nt < 4; nt++) {
                    const int p = nt >> 1, ix = (nt & 1) * 2;
                    uint32_t bbh[2] = {bh[p][ix], bh[p][ix + 1]};
                    uint32_t bbl[2] = {bl[p][ix], bl[p][ix + 1]};
                    mma16816(acc[mt][nt], ah, bbh);
                    mma16816(acc[mt][nt], ah, bbl);
                    mma16816(acc[mt][nt], al, bbh);
                }
            }
        }
    };

    // 3-stage pipeline, single sync per slab
    issue(0, 0);
    if (NSLAB > 1) issue(1, 1);
#pragma unroll 1
    for (int s = 0; s < NSLAB; s++) {
        if (s < NSLAB - 1) asm volatile("cp.async.wait_group 1;" ::: "memory");
        else               asm volatile("cp.async.wait_group 0;" ::: "memory");
        __syncthreads();
        compute(s % 3);
        if (s + 2 < NSLAB) issue(s + 2, (s + 2) % 3);
    }

    const int g = lane >> 2, c = lane & 3;

    if constexpr (EPI == 0) {
#pragma unroll
        for (int mt = 0; mt < 4; mt++) {
#pragma unroll
            for (int nt = 0; nt < 4; nt++) {
                const int col = col0 + warpN + nt * 8 + c * 2;
                const float bx = bias[col], by = bias[col + 1];
                const int rw = row0 + warpM + mt * 16 + g;
                float v0 = acc[mt][nt][0] + bx, v1 = acc[mt][nt][1] + by;
                float v2 = acc[mt][nt][2] + bx, v3 = acc[mt][nt][3] + by;
                if (RELU) {
                    v0 = fmaxf(v0, 0.f); v1 = fmaxf(v1, 0.f);
                    v2 = fmaxf(v2, 0.f); v3 = fmaxf(v3, 0.f);
                }
                __nv_bfloat16 h0 = __float2bfloat16(v0), h1 = __float2bfloat16(v1);
                __nv_bfloat16 h2 = __float2bfloat16(v2), h3 = __float2bfloat16(v3);
                *(uint32_t*)&CH[(size_t)rw * N + col] = pack2(h0, h1);
                *(uint32_t*)&CL[(size_t)rw * N + col] =
                    pack2(__float2bfloat16(v0 - __bfloat162float(h0)),
                          __float2bfloat16(v1 - __bfloat162float(h1)));
                *(uint32_t*)&CH[(size_t)(rw + 8) * N + col] = pack2(h2, h3);
                *(uint32_t*)&CL[(size_t)(rw + 8) * N + col] =
                    pack2(__float2bfloat16(v2 - __bfloat162float(h2)),
                          __float2bfloat16(v3 - __bfloat162float(h3)));
            }
        }
    }

    if constexpr (EPI == 1) {   // fused log_pis (N = 128, col0 = 0)
        float lsv[8]; float lsum = 0.f;
#pragma unroll
        for (int a = 0; a < 8; a++) {
            float l = tanhf(a_ls[a]);
            l = -5.0f + 3.5f * (l + 1.0f);
            lsv[a] = l; lsum += l;
        }
        const float cst = -lsum - 4.0f * 1.8378770664093453f;
        const float is0 = expf(-lsv[c * 2]), is1 = expf(-lsv[c * 2 + 1]);
#pragma unroll
        for (int mt = 0; mt < 4; mt++) {
            const int rw = row0 + warpM + mt * 16 + g;
            const float a00 = a_arr[(size_t)rw * 8 + c * 2];
            const float a01 = a_arr[(size_t)rw * 8 + c * 2 + 1];
            const float a10 = a_arr[(size_t)(rw + 8) * 8 + c * 2];
            const float a11 = a_arr[(size_t)(rw + 8) * 8 + c * 2 + 1];
#pragma unroll
            for (int nt = 0; nt < 4; nt++) {
                const int col = warpN + nt * 8 + c * 2;
                const float bx = bias[col], by = bias[col + 1];
                const int cc = (warpN >> 3) + nt;
                float m00 = fminf(fmaxf(acc[mt][nt][0] + bx, -10.f), 10.f);
                float m01 = fminf(fmaxf(acc[mt][nt][1] + by, -10.f), 10.f);
                float m10 = fminf(fmaxf(acc[mt][nt][2] + bx, -10.f), 10.f);
                float m11 = fminf(fmaxf(acc[mt][nt][3] + by, -10.f), 10.f);
                float z, s0, s1;
                z = (a00 - m00) * is0; s0 = z * z;
                z = (a01 - m01) * is1; s0 = fmaf(z, z, s0);
                z = (a10 - m10) * is0; s1 = z * z;
                z = (a11 - m11) * is1; s1 = fmaf(z, z, s1);
                s0 += __shfl_xor_sync(0xffffffffu, s0, 1);
                s0 += __shfl_xor_sync(0xffffffffu, s0, 2);
                s1 += __shfl_xor_sync(0xffffffffu, s1, 1);
                s1 += __shfl_xor_sync(0xffffffffu, s1, 2);
                if (c == 0) {
                    out_pis[(size_t)rw * 16 + cc]       = -0.5f * s0 + cst;
                    out_pis[(size_t)(rw + 8) * 16 + cc] = -0.5f * s1 + cst;
                }
            }
        }
    }

    if constexpr (EPI == 2) {   // fused log_softmax + entropy + tr0 (N = 272)
#pragma unroll
        for (int mt = 0; mt < 4; mt++) {
            const int rw = row0 + warpM + mt * 16 + g;
#pragma unroll
            for (int ntp = 0; ntp < 2; ntp++) {
                const int base = col0 + warpN + ntp * 16;
                if (NG && base >= N) continue;
                const int n0 = ntp * 2, n1 = ntp * 2 + 1;
                const int cA = base + c * 2, cB = base + 8 + c * 2;
                const float bv0 = bias[cA], bv1 = bias[cA + 1];
                const float bv2 = bias[cB], bv3 = bias[cB + 1];
                float v[2][4];
                v[0][0] = acc[mt][n0][0] + bv0; v[0][1] = acc[mt][n0][1] + bv1;
                v[0][2] = acc[mt][n1][0] + bv2; v[0][3] = acc[mt][n1][1] + bv3;
                v[1][0] = acc[mt][n0][2] + bv0; v[1][1] = acc[mt][n0][3] + bv1;
                v[1][2] = acc[mt][n1][2] + bv2; v[1][3] = acc[mt][n1][3] + bv3;
                const int gi = base >> 4;
#pragma unroll
                for (int r = 0; r < 2; r++) {
                    const int row = rw + r * 8;
                    float mx = fmaxf(fmaxf(v[r][0], v[r][1]), fmaxf(v[r][2], v[r][3]));
                    mx = fmaxf(mx, __shfl_xor_sync(0xffffffffu, mx, 1));
                    mx = fmaxf(mx, __shfl_xor_sync(0xffffffffu, mx, 2));
                    float s = 0.f, ws = 0.f;
#pragma unroll
                    for (int q = 0; q < 4; q++) {
                        float d = v[r][q] - mx;
                        float e = __expf(d);
                        s += e; ws = fmaf(d, e, ws);
                    }
                    s  += __shfl_xor_sync(0xffffffffu, s, 1);
                    s  += __shfl_xor_sync(0xffffffffu, s, 2);
                    ws += __shfl_xor_sync(0xffffffffu, ws, 1);
                    ws += __shfl_xor_sync(0xffffffffu, ws, 2);
                    const float ls = __logf(s), lse = mx + ls;
                    if (gi < 16) {
                        if (row >= 1) {
                            float* o = out_trs + (size_t)(row - 1) * 256 + gi * 16;
                            *(float2*)&o[c * 2]     = make_float2(v[r][0] - lse, v[r][1] - lse);
                            *(float2*)&o[8 + c * 2] = make_float2(v[r][2] - lse, v[r][3] - lse);
                            if (c == 0) out_ent[(size_t)(row - 1) * 16 + gi] = ls - ws / s;
                        }
                    } else if (row == 0) {
                        tr0[c * 2]     = v[r][0] - lse;
                        tr0[c * 2 + 1] = v[r][1] - lse;
                        tr0[8 + c * 2]     = v[r][2] - lse;
                        tr0[8 + c * 2 + 1] = v[r][3] - lse;
                    }
                }
            }
        }
    }
}

// ---------------- scan pass 1: factorized log-semiring matmul ----------------
// Thread (i,j) owns C[i][j] (register) and handles M entry M[j][i].
// (C o M)[i][j] = rmx_i + cmx_j + log( sum_k e^{C[i][k]-rmx_i} * e^{M[k][j]-cmx_j} )
// Both maxes are 16-lane shfl reductions; the contraction is a linear fp32 dot.
__global__ __launch_bounds__(256) void pass1_kernel(
    const float* __restrict__ trs, const float* __restrict__ pis, float* __restrict__ Cmat)
{
    const int g = blockIdx.x, tid = threadIdx.x;
    const int i = tid >> 4, j = tid & 15;
    const int t0 = g * CHUNK, t1 = min(t0 + CHUNK, NTRANS);
    const unsigned fm = 0xffffffffu;

    __shared__ float Ps[256];      // Ps[i*16+k] = e^{C[i][k]-rmx_i}
    __shared__ float QT[16 * 17];  // QT[j*17+k] = e^{M[k][j]-cmx_j}
    __shared__ float CMX[16];      // cmx per column

    float C = trs[(size_t)t0 * 256 + tid] + pis[(size_t)(t0 + 1) * 16 + j];

    for (int t = t0 + 1; t < t1; t++) {
        // This thread's M entry is M[j][i]  (row j, col i of M)
        float mv = trs[(size_t)t * 256 + j * 16 + i] + pis[(size_t)(t + 1) * 16 + i];

        // rmx for row i of C: reduce over the 16-lane half-warp (j varies)
        float rmx = C;
        rmx = fmaxf(rmx, __shfl_xor_sync(fm, rmx, 1));
        rmx = fmaxf(rmx, __shfl_xor_sync(fm, rmx, 2));
        rmx = fmaxf(rmx, __shfl_xor_sync(fm, rmx, 4));
        rmx = fmaxf(rmx, __shfl_xor_sync(fm, rmx, 8));
        // cmx for column i of M: same half-warp holds M[*][i]
        float cmx = mv;
        cmx = fmaxf(cmx, __shfl_xor_sync(fm, cmx, 1));
        cmx = fmaxf(cmx, __shfl_xor_sync(fm, cmx, 2));
        cmx = fmaxf(cmx, __shfl_xor_sync(fm, cmx, 4));
        cmx = fmaxf(cmx, __shfl_xor_sync(fm, cmx, 8));

        __syncthreads();            // prior iteration's reads of Ps/QT done
        Ps[tid] = __expf(C - rmx);
        QT[i * 17 + j] = __expf(mv - cmx);   // QT[col][row] of M
        if (j == 0) CMX[i] = cmx;
        __syncthreads();

        float dot = 0.f;
#pragma unroll
        for (int k = 0; k < 16; k++)
            dot = fmaf(Ps[i * 16 + k], QT[j * 17 + k], dot);
        C = rmx + CMX[j] + __logf(dot);
    }
    Cmat[g * 256 + tid] = C;
}

// ---------------- group prefix/suffix products ----------------
__global__ __launch_bounds__(256) void superprod_kernel(
    const float* __restrict__ Cmat, float* __restrict__ P, float* __restrict__ Suf)
{
    const int s = blockIdx.x & 15, dir = blockIdx.x >> 4, tid = threadIdx.x;
    const int i = tid >> 4, j = tid & 15;
    __shared__ float Cs[2][256], Ms[256];
    int cb = 0;
    if (dir == 0) {
        Cs[0][tid] = Cmat[(s*16) * 256 + tid];
        P[(s*16) * 256 + tid] = Cs[0][tid];
        for (int r = 1; r < 16; r++) {
            float mv = Cmat[(s*16+r) * 256 + tid];
            __syncthreads(); Ms[tid] = mv; __syncthreads();
            float tmp[16], mx = -FLT_MAX;
#pragma unroll
            for (int k = 0; k < 16; k++) { tmp[k] = Cs[cb][i*16+k] + Ms[k*16+j]; mx = fmaxf(mx, tmp[k]); }
            float ss = 0.f;
#pragma unroll
            for (int k = 0; k < 16; k++) ss += __expf(tmp[k] - mx);
            float res = mx + __logf(ss);
            Cs[cb^1][tid] = res;
            P[(s*16+r) * 256 + tid] = res;
            cb ^= 1;
        }
    } else {
        Cs[0][tid] = Cmat[(s*16+15) * 256 + tid];
        Suf[(s*16+15) * 256 + tid] = Cs[0][tid];
        for (int r = 14; r >= 0; r--) {
            float mv = Cmat[(s*16+r) * 256 + tid];
            __syncthreads(); Ms[tid] = mv; __syncthreads();
            float tmp[16], mx = -FLT_MAX;
#pragma unroll
            for (int k = 0; k < 16; k++) { tmp[k] = Ms[i*16+k] + Cs[cb][k*16+j]; mx = fmaxf(mx, tmp[k]); }
            float ss = 0.f;
#pragma unroll
            for (int k = 0; k < 16; k++) ss += __expf(tmp[k] - mx);
            float res = mx + __logf(ss);
            Cs[cb^1][tid] = res;
            Suf[(s*16+r) * 256 + tid] = res;
            cb ^= 1;
        }
    }
}

// ---------------- serial combine ----------------
__global__ void combine2_kernel(const float* __restrict__ P, const float* __restrict__ tr0,
                                const float* __restrict__ pis, float* __restrict__ Vs,
                                float* __restrict__ Wsv, float* __restrict__ out_beta)
{
    const int lane = threadIdx.x;
    if (lane >= 16) return;
    const unsigned mask = 0xFFFFu;
    if (blockIdx.x == 0) {
        float v = tr0[lane] + pis[lane];
        Vs[lane] = v;
        for (int s = 0; s < NSUPER; s++) {
            const float* S = P + (s*16+15) * 256;
            float tmp[16];
#pragma unroll
            for (int i = 0; i < 16; i++) tmp[i] = __shfl_sync(mask, v, i) + S[i*16+lane];
            float mx = tmp[0];
#pragma unroll
            for (int i = 1; i < 16; i++) mx = fmaxf(mx, tmp[i]);
            float ss = 0.f;
#pragma unroll
            for (int i = 0; i < 16; i++) ss += __expf(tmp[i] - mx);
            v = mx + __logf(ss);
            Vs[(s+1)*16 + lane] = v;
        }
    } else {
        float w = 0.f;
        Wsv[NSUPER*16 + lane] = 0.f;
        out_beta[(size_t)(T_LEN-1) * 16 + lane] = 0.f;
        for (int s = NSUPER - 1; s >= 0; s--) {
            const float* S = P + (s*16+15) * 256 + lane * 16;
            float tmp[16];
#pragma unroll
            for (int j = 0; j < 16; j++) tmp[j] = __shfl_sync(mask, w, j) + S[j];
            float mx = tmp[0];
#pragma unroll
            for (int j = 1; j < 16; j++) mx = fmaxf(mx, tmp[j]);
            float ss = 0.f;
#pragma unroll
            for (int j = 0; j < 16; j++) ss += __expf(tmp[j] - mx);
            w = mx + __logf(ss);
            Wsv[s*16 + lane] = w;
        }
    }
}

// ---------------- scan pass 2 ----------------
__global__ void pass2_kernel(const float* __restrict__ trs, const float* __restrict__ pis,
                             const float* __restrict__ P, const float* __restrict__ Suf,
                             const float* __restrict__ Vs, const float* __restrict__ Wsv,
                             float* __restrict__ out_alpha, float* __restrict__ out_beta)
{
    const int lane = threadIdx.x;
    if (lane >= 16) return;
    const unsigned mask = 0xFFFFu;
    const int b = blockIdx.x;
    if (b < G_CHUNKS) {
        const int g = b, s = g >> 4, r = g & 15;
        const int t0 = g * CHUNK, t1 = min(t0 + CHUNK, NTRANS);
        float v;
        {
            float vs = Vs[s*16 + lane];
            if (r == 0) v = vs;
            else {
                const float* Pm = P + (s*16 + r - 1) * 256;
                float tmp[16];
#pragma unroll
                for (int i = 0; i < 16; i++) tmp[i] = __shfl_sync(mask, vs, i) + Pm[i*16+lane];
                float mx = tmp[0];
#pragma unroll
                for (int i = 1; i < 16; i++) mx = fmaxf(mx, tmp[i]);
                float ss = 0.f;
#pragma unroll
                for (int i = 0; i < 16; i++) ss += __expf(tmp[i] - mx);
                v = mx + __logf(ss);
            }
        }
        if (g == 0) out_alpha[lane] = v;
        for (int t = t0; t < t1; t++) {
            const float* M = trs + (size_t)t * 256;
            float tmp[16];
#pragma unroll
            for (int i = 0; i < 16; i++) tmp[i] = __shfl_sync(mask, v, i) + M[i*16+lane];
            float mx = tmp[0];
#pragma unroll
            for (int i = 1; i < 16; i++) mx = fmaxf(mx, tmp[i]);
            float ss = 0.f;
#pragma unroll
            for (int i = 0; i < 16; i++) ss += __expf(tmp[i] - mx);
            v = mx + __logf(ss) + pis[(size_t)(t+1) * 16 + lane];
            out_alpha[(size_t)(t+1) * 16 + lane] = v;
        }
    } else {
        const int g = b - G_CHUNKS, s = g >> 4, r = g & 15;
        const int t0 = g * CHUNK, t1 = min(t0 + CHUNK, NTRANS);
        float w;
        {
            float wsv = Wsv[(s+1)*16 + lane];
            if (r == 15) w = wsv;
            else {
                const float* Sf = Suf + (s*16 + r + 1) * 256 + lane * 16;
                float tmp[16];
#pragma unroll
                for (int j = 0; j < 16; j++) tmp[j] = Sf[j] + __shfl_sync(mask, wsv, j);
                float mx = tmp[0];
#pragma unroll
                for (int j = 1; j < 16; j++) mx = fmaxf(mx, tmp[j]);
                float ss = 0.f;
#pragma unroll
                for (int j = 0; j < 16; j++) ss += __expf(tmp[j] - mx);
                w = mx + __logf(ss);
            }
        }
        for (int t = t1 - 1; t >= t0; t--) {
            const float* M = trs + (size_t)t * 256 + lane * 16;
            float u = w + pis[(size_t)(t+1) * 16 + lane];
            float tmp[16];
#pragma unroll
            for (int j = 0; j < 16; j++) tmp[j] = __shfl_sync(mask, u, j) + M[j];
            float mx = tmp[0];
#pragma unroll
            for (int j = 1; j < 16; j++) mx = fmaxf(mx, tmp[j]);
            float ss = 0.f;
#pragma unroll
            for (int j = 0; j < 16; j++) ss += __expf(tmp[j] - mx);
            w = mx + __logf(ss);
            out_beta[(size_t)t * 16 + lane] = w;
        }
    }
}

// ---------------- host launcher ----------------
extern "C" void kernel_launch(void* const* d_in, const int* in_sizes, int n_in,
                              void* d_out, int out_size)
{
    const float* s_arr = (const float*)d_in[0];
    const float* a_arr = (const float*)d_in[1];
    const float* pW1 = (const float*)d_in[2];  const float* pb1 = (const float*)d_in[3];
    const float* pW2 = (const float*)d_in[4];  const float* pb2 = (const float*)d_in[5];
    const float* pW3 = (const float*)d_in[6];  const float* pb3 = (const float*)d_in[7];
    const float* oW1 = (const float*)d_in[8];  const float* ob1 = (const float*)d_in[9];
    const float* oW2 = (const float*)d_in[10]; const float* ob2 = (const float*)d_in[11];
    const float* oW3 = (const float*)d_in[12]; const float* ob3 = (const float*)d_in[13];
    const float* als = (const float*)d_in[14];

    float* out = (float*)d_out;
    float* out_alpha = out + OFF_ALPHA;
    float* out_beta  = out + OFF_BETA;
    float* out_trs   = out + OFF_TRS;
    float* out_pis   = out + OFF_PIS;
    float* out_ent   = out + OFF_ENT;

    __nv_bfloat16 *sH, *sL, *h1pH, *h1pL, *h1oH, *h1oL, *h2pH, *h2pL, *h2oH, *h2oL, *wtH, *wtL;
    float *Cmat, *Pm, *Sf, *Vs, *Wsv, *tr0;
    cudaGetSymbolAddress((void**)&sH, g_sH);     cudaGetSymbolAddress((void**)&sL, g_sL);
    cudaGetSymbolAddress((void**)&h1pH, g_h1pH); cudaGetSymbolAddress((void**)&h1pL, g_h1pL);
    cudaGetSymbolAddress((void**)&h1oH, g_h1oH); cudaGetSymbolAddress((void**)&h1oL, g_h1oL);
    cudaGetSymbolAddress((void**)&h2pH, g_h2pH); cudaGetSymbolAddress((void**)&h2pL, g_h2pL);
    cudaGetSymbolAddress((void**)&h2oH, g_h2oH); cudaGetSymbolAddress((void**)&h2oL, g_h2oL);
    cudaGetSymbolAddress((void**)&wtH, g_wtH);   cudaGetSymbolAddress((void**)&wtL, g_wtL);
    cudaGetSymbolAddress((void**)&Cmat, g_Cmat);
    cudaGetSymbolAddress((void**)&Pm, g_P);
    cudaGetSymbolAddress((void**)&Sf, g_Suf);
    cudaGetSymbolAddress((void**)&Vs, g_Vs);
    cudaGetSymbolAddress((void**)&Wsv, g_Wsv);
    cudaGetSymbolAddress((void**)&tr0, g_tr0);

    cudaFuncSetAttribute(gemm7<64, 256, true, false, 0>,
                         cudaFuncAttributeMaxDynamicSharedMemorySize, SMEM_DYN);
    cudaFuncSetAttribute(gemm7<256, 256, true, false, 0>,
                         cudaFuncAttributeMaxDynamicSharedMemorySize, SMEM_DYN);
    cudaFuncSetAttribute(gemm7<256, 128, false, false, 1>,
                         cudaFuncAttributeMaxDynamicSharedMemorySize, SMEM_DYN);
    cudaFuncSetAttribute(gemm7<256, 272, false, true, 2>,
                         cudaFuncAttributeMaxDynamicSharedMemorySize, SMEM_DYN);

    prep_weights<<<(6 * WT_SZ + 255) / 256, 256>>>(pW1, oW1, pW2, oW2, pW3, oW3, wtH, wtL);
    prep_sact<<<(T_LEN * 64 + 255) / 256, 256>>>(s_arr, sH, sL);

    const int MB = T_LEN / 128;  // 512

    gemm7<64, 256, true, false, 0><<<dim3(MB, 2, 2), 256, SMEM_DYN>>>(
        sH, sL, wtH + 0*WT_SZ, wtL + 0*WT_SZ, pb1, h1pH, h1pL,
        sH, sL, wtH + 1*WT_SZ, wtL + 1*WT_SZ, ob1, h1oH, h1oL,
        nullptr, nullptr, nullptr, nullptr, nullptr, nullptr);
    gemm7<256, 256, true, false, 0><<<dim3(MB, 2, 2), 256, SMEM_DYN>>>(
        h1pH, h1pL, wtH + 2*WT_SZ, wtL + 2*WT_SZ, pb2, h2pH, h2pL,
        h1oH, h1oL, wtH + 3*WT_SZ, wtL + 3*WT_SZ, ob2, h2oH, h2oL,
        nullptr, nullptr, nullptr, nullptr, nullptr, nullptr);
    gemm7<256, 128, false, false, 1><<<dim3(MB, 1, 1), 256, SMEM_DYN>>>(
        h2pH, h2pL, wtH + 4*WT_SZ, wtL + 4*WT_SZ, pb3, nullptr, nullptr,
        h2pH, h2pL, wtH + 4*WT_SZ, wtL + 4*WT_SZ, pb3, nullptr, nullptr,
        a_arr, als, out_pis, nullptr, nullptr, nullptr);
    gemm7<256, 272, false, true, 2><<<dim3(MB, 3, 1), 256, SMEM_DYN>>>(
        h2oH, h2oL, wtH + 5*WT_SZ, wtL + 5*WT_SZ, ob3, nullptr, nullptr,
        h2oH, h2oL, wtH + 5*WT_SZ, wtL + 5*WT_SZ, ob3, nullptr, nullptr,
        nullptr, nullptr, nullptr, out_trs, out_ent, tr0);

    pass1_kernel<<<G_CHUNKS, 256>>>(out_trs, out_pis, Cmat);
    superprod_kernel<<<2 * NSUPER, 256>>>(Cmat, Pm, Sf);
    combine2_kernel<<<2, 32>>>(Pm, tr0, out_pis, Vs, Wsv, out_beta);
    pass2_kernel<<<2 * G_CHUNKS, 32>>>(out_trs, out_pis, Pm, Sf, Vs, Wsv,
                                       out_alpha, out_beta);
}